// round 4
// baseline (speedup 1.0000x reference)
#include <cuda_runtime.h>
#include <math.h>
#include <stdint.h>

#define B_  4
#define L_  2048
#define D_  1024
#define H_  16
#define DH  64
#define M_  (B_*L_)        /* 8192 */
#define NEG 1e7f

// -------------------- scratch --------------------
__device__ float g_qpe[M_*D_];   // tf32-rounded q+pe
__device__ float g_kpe[M_*D_];   // tf32-rounded k+pe
__device__ float g_vr [M_*D_];   // tf32-rounded v
__device__ float g_Qh[M_*D_];    // [B,H,L,DH]
__device__ float g_Kh[M_*D_];
__device__ float g_Vh[M_*D_];
__device__ float g_attn[M_*D_];  // [B,L,D], tf32-rounded
__device__ float g_Wt[4*D_*D_];  // transposed + tf32-rounded weights [N,K]

// -------------------- helpers --------------------
__device__ __forceinline__ unsigned f2tf(float x){
    unsigned r; asm("cvt.rna.tf32.f32 %0, %1;" : "=r"(r) : "f"(x)); return r;
}
__device__ __forceinline__ void mma8(float* c, const unsigned* a, const unsigned* b){
    asm volatile("mma.sync.aligned.m16n8k8.row.col.f32.tf32.tf32.f32 "
        "{%0,%1,%2,%3}, {%4,%5,%6,%7}, {%8,%9}, {%0,%1,%2,%3};"
        : "+f"(c[0]),"+f"(c[1]),"+f"(c[2]),"+f"(c[3])
        : "r"(a[0]),"r"(a[1]),"r"(a[2]),"r"(a[3]),"r"(b[0]),"r"(b[1]));
}

// -------------------- PE add (+ tf32 pre-round, + v copy) --------------------
__global__ void pe_add_kernel(const float* __restrict__ q, const float* __restrict__ k,
                              const float* __restrict__ v) {
    int i = blockIdx.x * blockDim.x + threadIdx.x;
    const int NF = D_ / 2;
    if (i >= M_ * NF) return;
    int row = i / NF;
    int f   = i - row * NF;
    int l   = row & (L_ - 1);
    const float kC = 9.210340371976184f / 512.0f;
    float ang = (float)l * expf(-(float)f * kC);
    float s, c;
    sincosf(ang, &s, &c);
    int base = row * D_ + 2 * f;
    g_qpe[base]   = __uint_as_float(f2tf(q[base]   + s));
    g_qpe[base+1] = __uint_as_float(f2tf(q[base+1] + c));
    g_kpe[base]   = __uint_as_float(f2tf(k[base]   + s));
    g_kpe[base+1] = __uint_as_float(f2tf(k[base+1] + c));
    g_vr[base]    = __uint_as_float(f2tf(v[base]));
    g_vr[base+1]  = __uint_as_float(f2tf(v[base+1]));
}

// -------------------- weight transpose (+ tf32 round) --------------------
__global__ void transpose_w4(const float* __restrict__ W0, const float* __restrict__ W1,
                             const float* __restrict__ W2, const float* __restrict__ W3){
    __shared__ float t[32][33];
    const float* W = (blockIdx.z==0)?W0:(blockIdx.z==1)?W1:(blockIdx.z==2)?W2:W3;
    float* O = g_Wt + (size_t)blockIdx.z * D_ * D_;
    int x0 = blockIdx.x*32, y0 = blockIdx.y*32;
    int tx = threadIdx.x, ty0 = threadIdx.y;
#pragma unroll
    for (int i=0;i<4;i++){ int ty=ty0+i*8; t[ty][tx] = W[(size_t)(y0+ty)*D_ + x0+tx]; }
    __syncthreads();
#pragma unroll
    for (int i=0;i<4;i++){ int ty=ty0+i*8;
        O[(size_t)(x0+ty)*D_ + y0+tx] = __uint_as_float(f2tf(t[tx][ty])); }
}

// -------------------- tf32 GEMM v3: permuted SW smem, 128-bit fragment loads --------
// C[8192,1024] = A @ W (+bias). Block 128x128, BK=32, 8 warps (2x4), warp 64x32.
// smem tile layout: 128 rows x 32 floats. float (r,k) at float-index
//   r*32 + ( ( (k&3) + 4*((k>>4)&1) ) ^ ((r&1)<<2) )*4 + ((k>>2)&3)
// so one uint4 per (row, lo/hi) covers a thread's a/b frags for 4 k8-steps.
#define G_SMEM (2*8192*4)    /* 2 stages x (A 4096 + B 4096 floats) = 64KB */

template<int HEADLAYOUT>
__global__ void __launch_bounds__(256, 1)
gemm_tf32v3(const float* __restrict__ A, const float* __restrict__ Wt,
            const float* __restrict__ bias, float* __restrict__ C){
    extern __shared__ __align__(16) float smem[];
    int tid=threadIdx.x, lane=tid&31;
    int warp=tid>>5, wm=warp>>2, wn=warp&3;
    int bm=blockIdx.y*128, bn=blockIdx.x*128;

    const float* Ab = A  + (size_t)bm * D_;
    const float* Bb = Wt + (size_t)bn * D_;

    float acc[4][4][4];
#pragma unroll
    for(int i=0;i<4;i++)
#pragma unroll
      for(int j=0;j<4;j++)
#pragma unroll
        for(int r=0;r<4;r++) acc[i][j][r]=0.f;

    float4 pa[4], pb[4];

    auto ldg_chunk=[&](int ch){
#pragma unroll
        for(int t=0;t<4;t++){
            int f4 = t*256 + tid;          // 0..1023
            int r = f4>>3, c4 = f4&7;
            pa[t] = *(const float4*)&Ab[(size_t)r*D_ + ch*32 + c4*4];
            pb[t] = *(const float4*)&Bb[(size_t)r*D_ + ch*32 + c4*4];
        }
    };
    auto sts_chunk=[&](int s){
        float* dA = smem + s*8192;
        float* dB = dA + 4096;
#pragma unroll
        for(int t=0;t<4;t++){
            int f4 = t*256 + tid;
            int r = f4>>3, c4 = f4&7;
            int e  = (r&1)<<2;
            int jj = c4&3;
            int hh = (c4>>2)<<2;           // 0 or 4
            float va[4]={pa[t].x,pa[t].y,pa[t].z,pa[t].w};
            float vb[4]={pb[t].x,pb[t].y,pb[t].z,pb[t].w};
#pragma unroll
            for(int i=0;i<4;i++){
                int sw = (i + hh) ^ e;
                dA[r*32 + sw*4 + jj] = va[i];
                dB[r*32 + sw*4 + jj] = vb[i];
            }
        }
    };

    ldg_chunk(0); sts_chunk(0); __syncthreads();

    int c = lane&3;
    for(int ch=0; ch<32; ch++){
        int cur = ch&1;
        if(ch<31) ldg_chunk(ch+1);

        const uint4* uA = (const uint4*)(smem + cur*8192);
        const uint4* uB = uA + 1024;

        // b fragments: 4 nt x (lo,hi) -> frags for 4 k8-steps
        uint4 bl[4], bh[4];
#pragma unroll
        for(int nt=0;nt<4;nt++){
            int n = wn*32 + nt*8 + (lane>>2);
            int e = (n&1)<<2;
            bl[nt] = uB[n*8 + (c ^ e)];
            bh[nt] = uB[n*8 + ((c+4) ^ e)];
        }
#pragma unroll
        for(int mt=0;mt<4;mt++){
            int r0 = wm*64 + mt*16 + (lane>>2);
            int r1 = r0 + 8;
            int e  = (r0&1)<<2;
            uint4 al0 = uA[r0*8 + (c ^ e)];
            uint4 al1 = uA[r1*8 + (c ^ e)];
            uint4 ah0 = uA[r0*8 + ((c+4) ^ e)];
            uint4 ah1 = uA[r1*8 + ((c+4) ^ e)];
            unsigned af[4][4] = {
                {al0.x, al1.x, al0.y, al1.y},
                {al0.z, al1.z, al0.w, al1.w},
                {ah0.x, ah1.x, ah0.y, ah1.y},
                {ah0.z, ah1.z, ah0.w, ah1.w}};
#pragma unroll
            for(int ks=0;ks<4;ks++){
                unsigned bf0[4][2] = {
                    {bl[0].x, bl[0].y}, {bl[1].x, bl[1].y},
                    {bl[2].x, bl[2].y}, {bl[3].x, bl[3].y}};
                unsigned bf1[4][2] = {
                    {bl[0].z, bl[0].w}, {bl[1].z, bl[1].w},
                    {bl[2].z, bl[2].w}, {bl[3].z, bl[3].w}};
                unsigned bf2[4][2] = {
                    {bh[0].x, bh[0].y}, {bh[1].x, bh[1].y},
                    {bh[2].x, bh[2].y}, {bh[3].x, bh[3].y}};
                unsigned bf3[4][2] = {
                    {bh[0].z, bh[0].w}, {bh[1].z, bh[1].w},
                    {bh[2].z, bh[2].w}, {bh[3].z, bh[3].w}};
                const unsigned (*bf)[2] = (ks==0)?bf0:(ks==1)?bf1:(ks==2)?bf2:bf3;
#pragma unroll
                for(int nt=0;nt<4;nt++)
                    mma8(acc[mt][nt], af[ks], bf[nt]);
            }
        }
        if(ch<31){ sts_chunk(1-cur); __syncthreads(); }
    }

    // epilogue
#pragma unroll
    for(int mt=0;mt<4;mt++){
        int r0 = bm + wm*64 + mt*16 + (lane>>2);
#pragma unroll
        for(int half=0;half<2;half++){
            int m = r0 + half*8;
            int bidx = m>>11, l = m&(L_-1);
#pragma unroll
            for(int nt=0;nt<4;nt++){
                int n = bn + wn*32 + nt*8 + 2*(lane&3);
                float2 bb = *(const float2*)&bias[n];
                float2 ov = make_float2(acc[mt][nt][half*2+0]+bb.x,
                                        acc[mt][nt][half*2+1]+bb.y);
                if(HEADLAYOUT){
                    int h=n>>6, dd=n&63;
                    *(float2*)&C[(size_t)((bidx*H_+h)*L_+l)*DH + dd]=ov;
                } else {
                    *(float2*)&C[(size_t)m*D_+n]=ov;
                }
            }
        }
    }
}

// -------------------- tf32 flash attention (R2, + rounded writeback) ------------
#define AST 68
#define ATTN_SMEM ((128*AST + 64*AST + 64*AST + 8*16*AST)*4 + 256)

__global__ void __launch_bounds__(256, 2)
attn_tf32(const unsigned char* __restrict__ pad, float* __restrict__ outp){
    extern __shared__ unsigned sm_u[];
    unsigned* sQ = sm_u;
    unsigned* sK = sQ + 128*AST;
    unsigned* sV = sK + 64*AST;
    unsigned* sP = sV + 64*AST;
    float* spad  = (float*)(sP + 8*16*AST);

    int tid=threadIdx.x, lane=tid&31, warp=tid>>5;
    int qt=blockIdx.x, bh=blockIdx.y;
    int b=bh>>4, h=bh&15;
    const float* Q = g_Qh + (size_t)bh*L_*DH;
    const float* K = g_Kh + (size_t)bh*L_*DH;
    const float* V = g_Vh + (size_t)bh*L_*DH;

#pragma unroll
    for(int t=0;t<8;t++){
        int idx=t*256+tid;
        int r=idx>>4, c4=idx&15;
        float4 v=*(const float4*)&Q[(size_t)(qt*128+r)*DH + c4*4];
        uint4 u; u.x=f2tf(v.x); u.y=f2tf(v.y); u.z=f2tf(v.z); u.w=f2tf(v.w);
        *(uint4*)&sQ[r*AST + c4*4]=u;
    }

    float m_[2]={-1e30f,-1e30f}, l_[2]={0.f,0.f};
    float o[8][4];
#pragma unroll
    for(int i=0;i<8;i++){o[i][0]=0.f;o[i][1]=0.f;o[i][2]=0.f;o[i][3]=0.f;}
    const float scale=0.125f;
    int r0g = qt*128 + warp*16 + (lane>>2);
    int r1g = r0g + 8;
    unsigned* pw = &sP[warp*16*AST];

    int nkt = 2*qt+2;
    for(int kt=0;kt<nkt;kt++){
        __syncthreads();
#pragma unroll
        for(int t=0;t<4;t++){
            int idx=t*256+tid; int r=idx>>4, c4=idx&15;
            float4 kv=*(const float4*)&K[(size_t)(kt*64+r)*DH + c4*4];
            uint4 uk; uk.x=f2tf(kv.x); uk.y=f2tf(kv.y); uk.z=f2tf(kv.z); uk.w=f2tf(kv.w);
            *(uint4*)&sK[r*AST+c4*4]=uk;
            float4 vv=*(const float4*)&V[(size_t)(kt*64+r)*DH + c4*4];
            uint4 uv; uv.x=f2tf(vv.x); uv.y=f2tf(vv.y); uv.z=f2tf(vv.z); uv.w=f2tf(vv.w);
            *(uint4*)&sV[r*AST+c4*4]=uv;
        }
        if(tid<64) spad[tid] = pad[b*L_ + kt*64 + tid] ? NEG : 0.f;
        __syncthreads();

        float s[8][4];
#pragma unroll
        for(int i=0;i<8;i++){s[i][0]=0.f;s[i][1]=0.f;s[i][2]=0.f;s[i][3]=0.f;}
#pragma unroll
        for(int ks=0;ks<8;ks++){
            unsigned a[4];
            const unsigned* qb=&sQ[(warp*16)*AST + ks*8];
            a[0]=qb[(lane>>2)*AST + (lane&3)];
            a[1]=qb[((lane>>2)+8)*AST + (lane&3)];
            a[2]=qb[(lane>>2)*AST + (lane&3)+4];
            a[3]=qb[((lane>>2)+8)*AST + (lane&3)+4];
#pragma unroll
            for(int nt=0;nt<8;nt++){
                unsigned bfr[2];
                const unsigned* kb=&sK[(nt*8+(lane>>2))*AST + ks*8];
                bfr[0]=kb[lane&3];
                bfr[1]=kb[(lane&3)+4];
                mma8(s[nt], a, bfr);
            }
        }

        float rmax0=-1e30f, rmax1=-1e30f;
#pragma unroll
        for(int nt=0;nt<8;nt++){
            int cl = nt*8 + 2*(lane&3);
            int c0 = kt*64 + cl, c1 = c0+1;
            float ms0=spad[cl], ms1=spad[cl+1];
            float v0=s[nt][0]*scale - ms0; if(c0>r0g) v0-=NEG;
            float v1=s[nt][1]*scale - ms1; if(c1>r0g) v1-=NEG;
            float v2=s[nt][2]*scale - ms0; if(c0>r1g) v2-=NEG;
            float v3=s[nt][3]*scale - ms1; if(c1>r1g) v3-=NEG;
            s[nt][0]=v0; s[nt][1]=v1; s[nt][2]=v2; s[nt][3]=v3;
            rmax0=fmaxf(rmax0,fmaxf(v0,v1));
            rmax1=fmaxf(rmax1,fmaxf(v2,v3));
        }
        rmax0=fmaxf(rmax0,__shfl_xor_sync(0xffffffffu,rmax0,1));
        rmax0=fmaxf(rmax0,__shfl_xor_sync(0xffffffffu,rmax0,2));
        rmax1=fmaxf(rmax1,__shfl_xor_sync(0xffffffffu,rmax1,1));
        rmax1=fmaxf(rmax1,__shfl_xor_sync(0xffffffffu,rmax1,2));

        float mn0=fmaxf(m_[0],rmax0), mn1=fmaxf(m_[1],rmax1);
        float corr0=__expf(m_[0]-mn0), corr1=__expf(m_[1]-mn1);
        m_[0]=mn0; m_[1]=mn1;
        float rs0=0.f, rs1=0.f;
#pragma unroll
        for(int nt=0;nt<8;nt++){
            s[nt][0]=__expf(s[nt][0]-mn0); rs0+=s[nt][0];
            s[nt][1]=__expf(s[nt][1]-mn0); rs0+=s[nt][1];
            s[nt][2]=__expf(s[nt][2]-mn1); rs1+=s[nt][2];
            s[nt][3]=__expf(s[nt][3]-mn1); rs1+=s[nt][3];
        }
        rs0+=__shfl_xor_sync(0xffffffffu,rs0,1);
        rs0+=__shfl_xor_sync(0xffffffffu,rs0,2);
        rs1+=__shfl_xor_sync(0xffffffffu,rs1,1);
        rs1+=__shfl_xor_sync(0xffffffffu,rs1,2);
        l_[0]=l_[0]*corr0+rs0; l_[1]=l_[1]*corr1+rs1;
#pragma unroll
        for(int nt=0;nt<8;nt++){
            o[nt][0]*=corr0; o[nt][1]*=corr0;
            o[nt][2]*=corr1; o[nt][3]*=corr1;
        }

#pragma unroll
        for(int nt=0;nt<8;nt++){
            int cl = nt*8 + 2*(lane&3);
            pw[(lane>>2)*AST + cl]     = f2tf(s[nt][0]);
            pw[(lane>>2)*AST + cl+1]   = f2tf(s[nt][1]);
            pw[((lane>>2)+8)*AST + cl]   = f2tf(s[nt][2]);
            pw[((lane>>2)+8)*AST + cl+1] = f2tf(s[nt][3]);
        }
        __syncwarp();

#pragma unroll
        for(int ks=0;ks<8;ks++){
            unsigned a[4];
            const unsigned* pb=&pw[ks*8];
            a[0]=pb[(lane>>2)*AST + (lane&3)];
            a[1]=pb[((lane>>2)+8)*AST + (lane&3)];
            a[2]=pb[(lane>>2)*AST + (lane&3)+4];
            a[3]=pb[((lane>>2)+8)*AST + (lane&3)+4];
#pragma unroll
            for(int nt=0;nt<8;nt++){
                unsigned bfr[2];
                bfr[0]=sV[(ks*8+(lane&3))*AST + nt*8 + (lane>>2)];
                bfr[1]=sV[(ks*8+(lane&3)+4)*AST + nt*8 + (lane>>2)];
                mma8(o[nt], a, bfr);
            }
        }
    }

    float inv0=1.f/l_[0], inv1=1.f/l_[1];
#pragma unroll
    for(int nt=0;nt<8;nt++){
        int dd = nt*8 + 2*(lane&3);
        float2 v0=make_float2(__uint_as_float(f2tf(o[nt][0]*inv0)),
                              __uint_as_float(f2tf(o[nt][1]*inv0)));
        float2 v1=make_float2(__uint_as_float(f2tf(o[nt][2]*inv1)),
                              __uint_as_float(f2tf(o[nt][3]*inv1)));
        *(float2*)&outp[(size_t)(b*L_+r0g)*D_ + h*DH + dd]=v0;
        *(float2*)&outp[(size_t)(b*L_+r1g)*D_ + h*DH + dd]=v1;
    }
}

// -------------------- launch --------------------
extern "C" void kernel_launch(void* const* d_in, const int* in_sizes, int n_in,
                              void* d_out, int out_size) {
    const float* q  = (const float*)d_in[0];
    const float* k  = (const float*)d_in[1];
    const float* v  = (const float*)d_in[2];
    const unsigned char* pad = (const unsigned char*)d_in[3];
    const float* Wq = (const float*)d_in[4];
    const float* bq = (const float*)d_in[5];
    const float* Wk = (const float*)d_in[6];
    const float* bk = (const float*)d_in[7];
    const float* Wv = (const float*)d_in[8];
    const float* bv = (const float*)d_in[9];
    const float* Wo = (const float*)d_in[10];
    const float* bo = (const float*)d_in[11];
    float* out = (float*)d_out;

    float *p_qpe, *p_kpe, *p_vr, *p_Qh, *p_Kh, *p_Vh, *p_attn, *p_Wt;
    cudaGetSymbolAddress((void**)&p_qpe,  g_qpe);
    cudaGetSymbolAddress((void**)&p_kpe,  g_kpe);
    cudaGetSymbolAddress((void**)&p_vr,   g_vr);
    cudaGetSymbolAddress((void**)&p_Qh,   g_Qh);
    cudaGetSymbolAddress((void**)&p_Kh,   g_Kh);
    cudaGetSymbolAddress((void**)&p_Vh,   g_Vh);
    cudaGetSymbolAddress((void**)&p_attn, g_attn);
    cudaGetSymbolAddress((void**)&p_Wt,   g_Wt);

    cudaFuncSetAttribute(attn_tf32, cudaFuncAttributeMaxDynamicSharedMemorySize, ATTN_SMEM);
    cudaFuncSetAttribute(gemm_tf32v3<0>, cudaFuncAttributeMaxDynamicSharedMemorySize, G_SMEM);
    cudaFuncSetAttribute(gemm_tf32v3<1>, cudaFuncAttributeMaxDynamicSharedMemorySize, G_SMEM);

    // 0) weight transposes (+ tf32 round)
    transpose_w4<<<dim3(32,32,4), dim3(32,8)>>>(Wq, Wk, Wv, Wo);

    // 1) positional encodings (+ tf32 pre-round of q+pe, k+pe, v)
    int pe_threads = M_ * (D_ / 2);
    pe_add_kernel<<<(pe_threads + 255) / 256, 256>>>(q, k, v);

    // 2) QKV projections -> head layout
    dim3 gg(D_ / 128, M_ / 128), blk(256);
    gemm_tf32v3<1><<<gg, blk, G_SMEM>>>(p_qpe, p_Wt + 0*(size_t)D_*D_, bq, p_Qh);
    gemm_tf32v3<1><<<gg, blk, G_SMEM>>>(p_kpe, p_Wt + 1*(size_t)D_*D_, bk, p_Kh);
    gemm_tf32v3<1><<<gg, blk, G_SMEM>>>(p_vr,  p_Wt + 2*(size_t)D_*D_, bv, p_Vh);

    // 3) fused causal attention
    attn_tf32<<<dim3(L_ / 128, B_ * H_), 256, ATTN_SMEM>>>(pad, p_attn);

    // 4) output projection
    gemm_tf32v3<0><<<gg, blk, G_SMEM>>>(p_attn, p_Wt + 3*(size_t)D_*D_, bo, out);
}

// round 5
// speedup vs baseline: 2.2866x; 2.2866x over previous
#include <cuda_runtime.h>
#include <cuda_fp16.h>
#include <math.h>
#include <stdint.h>

#define B_  4
#define L_  2048
#define D_  1024
#define H_  16
#define DH  64
#define M_  (B_*L_)        /* 8192 */
#define NEG 1e7f

// -------------------- scratch (all half) --------------------
__device__ __half g_qpe[M_*D_];
__device__ __half g_kpe[M_*D_];
__device__ __half g_vr [M_*D_];
__device__ __half g_Qh[M_*D_];    // [B,H,L,DH]
__device__ __half g_Kh[M_*D_];
__device__ __half g_Vh[M_*D_];
__device__ __half g_attn[M_*D_];  // [B,L,D]
__device__ __half g_Wt[4*D_*D_];  // transposed weights [N][K]

// -------------------- helpers --------------------
__device__ __forceinline__ void mma16(float* c, const unsigned* a, const unsigned* b){
    asm volatile("mma.sync.aligned.m16n8k16.row.col.f32.f16.f16.f32 "
        "{%0,%1,%2,%3}, {%4,%5,%6,%7}, {%8,%9}, {%0,%1,%2,%3};"
        : "+f"(c[0]),"+f"(c[1]),"+f"(c[2]),"+f"(c[3])
        : "r"(a[0]),"r"(a[1]),"r"(a[2]),"r"(a[3]),"r"(b[0]),"r"(b[1]));
}
__device__ __forceinline__ void ldsm_x4(unsigned* r, uint32_t a){
    asm volatile("ldmatrix.sync.aligned.m8n8.x4.shared.b16 {%0,%1,%2,%3}, [%4];"
        : "=r"(r[0]),"=r"(r[1]),"=r"(r[2]),"=r"(r[3]) : "r"(a));
}
__device__ __forceinline__ void ldsm_x2(unsigned* r, uint32_t a){
    asm volatile("ldmatrix.sync.aligned.m8n8.x2.shared.b16 {%0,%1}, [%2];"
        : "=r"(r[0]),"=r"(r[1]) : "r"(a));
}
__device__ __forceinline__ void ldsm_x2t(unsigned* r, uint32_t a){
    asm volatile("ldmatrix.sync.aligned.m8n8.x2.trans.shared.b16 {%0,%1}, [%2];"
        : "=r"(r[0]),"=r"(r[1]) : "r"(a));
}
__device__ __forceinline__ uint32_t smem_u32(const void* p){
    uint32_t a; asm("{ .reg .u64 t; cvta.to.shared.u64 t, %1; cvt.u32.u64 %0, t; }"
                    : "=r"(a) : "l"(p)); return a;
}

// -------------------- PE add (fp32 math -> half) --------------------
__global__ void pe_add_kernel(const float* __restrict__ q, const float* __restrict__ k,
                              const float* __restrict__ v) {
    int i = blockIdx.x * blockDim.x + threadIdx.x;
    const int NF = D_ / 2;
    if (i >= M_ * NF) return;
    int row = i / NF;
    int f   = i - row * NF;
    int l   = row & (L_ - 1);
    const float kC = 9.210340371976184f / 512.0f;
    float ang = (float)l * expf(-(float)f * kC);
    float s, c;
    sincosf(ang, &s, &c);
    int base = row * D_ + 2 * f;
    *(half2*)&g_qpe[base] = __floats2half2_rn(q[base] + s, q[base+1] + c);
    *(half2*)&g_kpe[base] = __floats2half2_rn(k[base] + s, k[base+1] + c);
    *(half2*)&g_vr[base]  = __floats2half2_rn(v[base],     v[base+1]);
}

// -------------------- weight transpose -> half [N][K] --------------------
__global__ void transpose_w4(const float* __restrict__ W0, const float* __restrict__ W1,
                             const float* __restrict__ W2, const float* __restrict__ W3){
    __shared__ float t[32][33];
    const float* W = (blockIdx.z==0)?W0:(blockIdx.z==1)?W1:(blockIdx.z==2)?W2:W3;
    __half* O = g_Wt + (size_t)blockIdx.z * D_ * D_;
    int x0 = blockIdx.x*32, y0 = blockIdx.y*32;
    int tx = threadIdx.x, ty0 = threadIdx.y;   // (32, 8)
#pragma unroll
    for (int i=0;i<4;i++){ int ty=ty0+i*8; t[ty][tx] = W[(size_t)(y0+ty)*D_ + x0+tx]; }
    __syncthreads();
#pragma unroll
    for (int i=0;i<2;i++){
        int kk = ty0 + i*8;   // k-pair 0..15
        half2 h = __floats2half2_rn(t[2*kk][tx], t[2*kk+1][tx]);
        *(half2*)&O[(size_t)(x0+tx)*D_ + y0 + 2*kk] = h;
    }
}

// -------------------- fp16 GEMM: C = A[8192,1024] @ W^T(+bias) --------------------
// Block 128x128, BK=32, 8 warps (2x4), warp 64x32. 2-stage smem (32KB).
// smem tile: [row][32 halves]; 16B chunk c of row r stored at r*64 + 16*(c ^ ((r>>1)&3)).
#define GS 16384
#define G_SMEM (2*GS)

template<int HEADLAYOUT>
__global__ void __launch_bounds__(256, 2)
gemm_h(const __half* __restrict__ A, const __half* __restrict__ Wt,
       const float* __restrict__ bias, void* __restrict__ Cv){
    extern __shared__ __align__(128) char smem[];
    uint32_t sb = smem_u32(smem);
    int tid=threadIdx.x, lane=tid&31;
    int warp=tid>>5, wm=warp>>2, wn=warp&3;
    int bm=blockIdx.y*128, bn=blockIdx.x*128;

    const __half* Ab = A  + (size_t)bm * D_;
    const __half* Bb = Wt + (size_t)bn * D_;

    float acc[4][4][4];
#pragma unroll
    for(int i=0;i<4;i++)
#pragma unroll
      for(int j=0;j<4;j++)
#pragma unroll
        for(int r=0;r<4;r++) acc[i][j][r]=0.f;

    // producer mapping: thread -> (row, chunk-pair)
    int pr = tid>>1;
    int pc = (tid&1)*2;
    int psw = (pr>>1)&3;
    uint32_t stA0 = pr*64 + 16*((pc+0)^psw);
    uint32_t stA1 = pr*64 + 16*((pc+1)^psw);

    // fragment addresses (stage-relative)
    int l7=lane&7, g8=(lane>>3)&1, k8a=lane>>4, k8b=(lane>>3)&1;
    uint32_t aOff[4]; int aSwz[4];
#pragma unroll
    for(int mt=0;mt<4;mt++){
        int r = wm*64 + mt*16 + l7 + g8*8;
        aOff[mt] = r*64; aSwz[mt] = (r>>1)&3;
    }
    uint32_t bOff[4]; int bSwz[4];
#pragma unroll
    for(int nt=0;nt<4;nt++){
        int n = wn*32 + nt*8 + l7;
        bOff[nt] = 8192u + n*64; bSwz[nt] = (n>>1)&3;
    }

    uint4 pa[2], pb[2];
    auto ldg=[&](int ch){
        const uint4* ap = (const uint4*)(Ab + (size_t)pr*D_ + ch*32 + pc*8);
        pa[0]=ap[0]; pa[1]=ap[1];
        const uint4* bp = (const uint4*)(Bb + (size_t)pr*D_ + ch*32 + pc*8);
        pb[0]=bp[0]; pb[1]=bp[1];
    };
    auto sts=[&](int s){
        char* d = smem + s*GS;
        *(uint4*)(d + stA0) = pa[0];
        *(uint4*)(d + stA1) = pa[1];
        *(uint4*)(d + 8192 + stA0) = pb[0];
        *(uint4*)(d + 8192 + stA1) = pb[1];
    };

    ldg(0); sts(0); __syncthreads();

    for(int ch=0; ch<32; ch++){
        int cur = ch&1;
        uint32_t so = sb + cur*GS;
        if(ch<31) ldg(ch+1);
#pragma unroll
        for(int ks=0;ks<2;ks++){
            unsigned bf[4][2];
#pragma unroll
            for(int nt=0;nt<4;nt++)
                ldsm_x2(bf[nt], so + bOff[nt] + 16*((2*ks + k8b) ^ bSwz[nt]));
#pragma unroll
            for(int mt=0;mt<4;mt++){
                unsigned af[4];
                ldsm_x4(af, so + aOff[mt] + 16*((2*ks + k8a) ^ aSwz[mt]));
#pragma unroll
                for(int nt=0;nt<4;nt++)
                    mma16(acc[mt][nt], af, bf[nt]);
            }
        }
        if(ch<31){ sts(1-cur); __syncthreads(); }
    }

    // epilogue
#pragma unroll
    for(int mt=0;mt<4;mt++){
        int r0 = bm + wm*64 + mt*16 + (lane>>2);
#pragma unroll
        for(int hf=0;hf<2;hf++){
            int m = r0 + hf*8;
            int bidx = m>>11, l = m&(L_-1);
#pragma unroll
            for(int nt=0;nt<4;nt++){
                int n = bn + wn*32 + nt*8 + 2*(lane&3);
                float2 bb = *(const float2*)&bias[n];
                float v0 = acc[mt][nt][hf*2+0] + bb.x;
                float v1 = acc[mt][nt][hf*2+1] + bb.y;
                if(HEADLAYOUT){
                    int h=n>>6, dd=n&63;
                    *(half2*)&((__half*)Cv)[(size_t)((bidx*H_+h)*L_+l)*DH + dd] =
                        __floats2half2_rn(v0, v1);
                } else {
                    float2 ov = make_float2(v0, v1);
                    *(float2*)&((float*)Cv)[(size_t)m*D_ + n] = ov;
                }
            }
        }
    }
}

// -------------------- fp16 flash attention --------------------
// 128-row Q tiles, 64-key K/V tiles, 8 warps (16 rows each).
// smem rows are 64 halves = 128B, 16B chunk c of row r at r*128 + 16*(c ^ (r&7)).
#define AQ 0
#define AK 16384
#define AV 24576
#define AP 32768            /* per-warp 16x64 halves: warp*2048 */
#define APAD 49152
#define ATTN_SMEM (APAD + 256)

__global__ void __launch_bounds__(256, 2)
attn_h(const unsigned char* __restrict__ pad, __half* __restrict__ outp){
    extern __shared__ __align__(128) char smem[];
    uint32_t sb = smem_u32(smem);
    float* spad = (float*)(smem + APAD);

    int tid=threadIdx.x, lane=tid&31, warp=tid>>5;
    int qt=blockIdx.x, bh=blockIdx.y;
    int b=bh>>4, h=bh&15;
    const __half* Q = g_Qh + (size_t)bh*L_*DH;
    const __half* K = g_Kh + (size_t)bh*L_*DH;
    const __half* V = g_Vh + (size_t)bh*L_*DH;

    // load Q tile: 128 rows x 8 chunks
#pragma unroll
    for(int t=0;t<4;t++){
        int idx=t*256+tid;
        int r=idx>>3, c=idx&7;
        uint4 u = *(const uint4*)(Q + (size_t)(qt*128+r)*DH + c*8);
        *(uint4*)(smem + AQ + r*128 + 16*(c ^ (r&7))) = u;
    }

    // fragment address precompute
    int l7=lane&7, g8=(lane>>3)&1, k8=lane>>4, k8b=(lane>>3)&1;
    int rqa = warp*16 + l7 + g8*8;
    uint32_t qOff = AQ + rqa*128;  int qSwz = rqa&7;
    uint32_t kOff[8]; int kSwz[8];
#pragma unroll
    for(int nt=0;nt<8;nt++){
        int n = nt*8 + l7;
        kOff[nt] = AK + n*128; kSwz[nt] = n&7;
    }
    int rpa = l7 + g8*8;
    uint32_t pOff = AP + warp*2048 + rpa*128;  int pSwz = rpa&7;

    int rq0 = lane>>2;                     // warp-local row
    int pc4 = 4*(lane&3);
    uint32_t pst0 = AP + warp*2048 + rq0*128;
    uint32_t pst1 = pst0 + 8*128;
    int pstSwz = rq0&7;                    // (rq0+8)&7 identical

    float m_[2]={-1e30f,-1e30f}, l_[2]={0.f,0.f};
    float o[8][4];
#pragma unroll
    for(int i=0;i<8;i++){o[i][0]=0.f;o[i][1]=0.f;o[i][2]=0.f;o[i][3]=0.f;}
    const float scale=0.125f;
    int r0g = qt*128 + warp*16 + rq0;
    int r1g = r0g + 8;

    int nkt = 2*qt+2;
    for(int kt=0;kt<nkt;kt++){
        __syncthreads();
        // load K,V tiles: 64 rows x 8 chunks each
#pragma unroll
        for(int t=0;t<2;t++){
            int idx=t*256+tid;
            int r=idx>>3, c=idx&7;
            uint32_t dsto = r*128 + 16*(c ^ (r&7));
            uint4 uk = *(const uint4*)(K + (size_t)(kt*64+r)*DH + c*8);
            *(uint4*)(smem + AK + dsto) = uk;
            uint4 uv = *(const uint4*)(V + (size_t)(kt*64+r)*DH + c*8);
            *(uint4*)(smem + AV + dsto) = uv;
        }
        if(tid<64) spad[tid] = pad[b*L_ + kt*64 + tid] ? NEG : 0.f;
        __syncthreads();

        // ---- S = Q K^T ----
        float s[8][4];
#pragma unroll
        for(int i=0;i<8;i++){s[i][0]=0.f;s[i][1]=0.f;s[i][2]=0.f;s[i][3]=0.f;}
#pragma unroll
        for(int ks=0;ks<4;ks++){
            unsigned af[4];
            ldsm_x4(af, sb + qOff + 16*((2*ks + k8) ^ qSwz));
#pragma unroll
            for(int nt=0;nt<8;nt++){
                unsigned bf[2];
                ldsm_x2(bf, sb + kOff[nt] + 16*((2*ks + k8b) ^ kSwz[nt]));
                mma16(s[nt], af, bf);
            }
        }

        // ---- scale + mask + online softmax (fp32) ----
        float rmax0=-1e30f, rmax1=-1e30f;
#pragma unroll
        for(int nt=0;nt<8;nt++){
            int cl = nt*8 + 2*(lane&3);
            int c0 = kt*64 + cl, c1 = c0+1;
            float ms0=spad[cl], ms1=spad[cl+1];
            float v0=s[nt][0]*scale - ms0; if(c0>r0g) v0-=NEG;
            float v1=s[nt][1]*scale - ms1; if(c1>r0g) v1-=NEG;
            float v2=s[nt][2]*scale - ms0; if(c0>r1g) v2-=NEG;
            float v3=s[nt][3]*scale - ms1; if(c1>r1g) v3-=NEG;
            s[nt][0]=v0; s[nt][1]=v1; s[nt][2]=v2; s[nt][3]=v3;
            rmax0=fmaxf(rmax0,fmaxf(v0,v1));
            rmax1=fmaxf(rmax1,fmaxf(v2,v3));
        }
        rmax0=fmaxf(rmax0,__shfl_xor_sync(0xffffffffu,rmax0,1));
        rmax0=fmaxf(rmax0,__shfl_xor_sync(0xffffffffu,rmax0,2));
        rmax1=fmaxf(rmax1,__shfl_xor_sync(0xffffffffu,rmax1,1));
        rmax1=fmaxf(rmax1,__shfl_xor_sync(0xffffffffu,rmax1,2));

        float mn0=fmaxf(m_[0],rmax0), mn1=fmaxf(m_[1],rmax1);
        float corr0=__expf(m_[0]-mn0), corr1=__expf(m_[1]-mn1);
        m_[0]=mn0; m_[1]=mn1;
        float rs0=0.f, rs1=0.f;
#pragma unroll
        for(int nt=0;nt<8;nt++){
            s[nt][0]=__expf(s[nt][0]-mn0); rs0+=s[nt][0];
            s[nt][1]=__expf(s[nt][1]-mn0); rs0+=s[nt][1];
            s[nt][2]=__expf(s[nt][2]-mn1); rs1+=s[nt][2];
            s[nt][3]=__expf(s[nt][3]-mn1); rs1+=s[nt][3];
        }
        rs0+=__shfl_xor_sync(0xffffffffu,rs0,1);
        rs0+=__shfl_xor_sync(0xffffffffu,rs0,2);
        rs1+=__shfl_xor_sync(0xffffffffu,rs1,1);
        rs1+=__shfl_xor_sync(0xffffffffu,rs1,2);
        l_[0]=l_[0]*corr0+rs0; l_[1]=l_[1]*corr1+rs1;
#pragma unroll
        for(int nt=0;nt<8;nt++){
            o[nt][0]*=corr0; o[nt][1]*=corr0;
            o[nt][2]*=corr1; o[nt][3]*=corr1;
        }

        // ---- P -> warp-private smem (half2) ----
#pragma unroll
        for(int nt=0;nt<8;nt++){
            uint32_t co = 16*(nt ^ pstSwz) + pc4;
            *(half2*)(smem + pst0 + co) = __floats2half2_rn(s[nt][0], s[nt][1]);
            *(half2*)(smem + pst1 + co) = __floats2half2_rn(s[nt][2], s[nt][3]);
        }
        __syncwarp();

        // ---- O += P V ----
#pragma unroll
        for(int ks=0;ks<4;ks++){
            unsigned pf[4];
            ldsm_x4(pf, sb + pOff + 16*((2*ks + k8) ^ pSwz));
            int vrow = ks*16 + l7 + k8b*8;
            uint32_t vbase = AV + vrow*128;
            int vSwz = vrow&7;
#pragma unroll
            for(int nt=0;nt<8;nt++){
                unsigned bf[2];
                ldsm_x2t(bf, sb + vbase + 16*(nt ^ vSwz));
                mma16(o[nt], pf, bf);
            }
        }
    }

    // ---- normalize + write half [B,L,D] ----
    float inv0=1.f/l_[0], inv1=1.f/l_[1];
#pragma unroll
    for(int nt=0;nt<8;nt++){
        int dd = nt*8 + 2*(lane&3);
        *(half2*)&outp[(size_t)(b*L_+r0g)*D_ + h*DH + dd] =
            __floats2half2_rn(o[nt][0]*inv0, o[nt][1]*inv0);
        *(half2*)&outp[(size_t)(b*L_+r1g)*D_ + h*DH + dd] =
            __floats2half2_rn(o[nt][2]*inv1, o[nt][3]*inv1);
    }
}

// -------------------- launch --------------------
extern "C" void kernel_launch(void* const* d_in, const int* in_sizes, int n_in,
                              void* d_out, int out_size) {
    const float* q  = (const float*)d_in[0];
    const float* k  = (const float*)d_in[1];
    const float* v  = (const float*)d_in[2];
    const unsigned char* pad = (const unsigned char*)d_in[3];
    const float* Wq = (const float*)d_in[4];
    const float* bq = (const float*)d_in[5];
    const float* Wk = (const float*)d_in[6];
    const float* bk = (const float*)d_in[7];
    const float* Wv = (const float*)d_in[8];
    const float* bv = (const float*)d_in[9];
    const float* Wo = (const float*)d_in[10];
    const float* bo = (const float*)d_in[11];
    float* out = (float*)d_out;

    __half *p_qpe, *p_kpe, *p_vr, *p_Qh, *p_Kh, *p_Vh, *p_attn, *p_Wt;
    cudaGetSymbolAddress((void**)&p_qpe,  g_qpe);
    cudaGetSymbolAddress((void**)&p_kpe,  g_kpe);
    cudaGetSymbolAddress((void**)&p_vr,   g_vr);
    cudaGetSymbolAddress((void**)&p_Qh,   g_Qh);
    cudaGetSymbolAddress((void**)&p_Kh,   g_Kh);
    cudaGetSymbolAddress((void**)&p_Vh,   g_Vh);
    cudaGetSymbolAddress((void**)&p_attn, g_attn);
    cudaGetSymbolAddress((void**)&p_Wt,   g_Wt);

    cudaFuncSetAttribute(attn_h, cudaFuncAttributeMaxDynamicSharedMemorySize, ATTN_SMEM);
    cudaFuncSetAttribute(gemm_h<0>, cudaFuncAttributeMaxDynamicSharedMemorySize, G_SMEM);
    cudaFuncSetAttribute(gemm_h<1>, cudaFuncAttributeMaxDynamicSharedMemorySize, G_SMEM);

    // 0) weight transposes -> half [N][K]
    transpose_w4<<<dim3(32,32,4), dim3(32,8)>>>(Wq, Wk, Wv, Wo);

    // 1) positional encodings -> half
    int pe_threads = M_ * (D_ / 2);
    pe_add_kernel<<<(pe_threads + 255) / 256, 256>>>(q, k, v);

    // 2) QKV projections -> head layout (half)
    dim3 gg(D_ / 128, M_ / 128), blk(256);
    gemm_h<1><<<gg, blk, G_SMEM>>>(p_qpe, p_Wt + 0*(size_t)D_*D_, bq, p_Qh);
    gemm_h<1><<<gg, blk, G_SMEM>>>(p_kpe, p_Wt + 1*(size_t)D_*D_, bk, p_Kh);
    gemm_h<1><<<gg, blk, G_SMEM>>>(p_vr,  p_Wt + 2*(size_t)D_*D_, bv, p_Vh);

    // 3) fused causal flash attention (fp16 tensor cores)
    attn_h<<<dim3(L_ / 128, B_ * H_), 256, ATTN_SMEM>>>(pad, p_attn);

    // 4) output projection -> fp32 d_out
    gemm_h<0><<<gg, blk, G_SMEM>>>(p_attn, p_Wt + 3*(size_t)D_*D_, bo, out);
}

// round 6
// speedup vs baseline: 2.6927x; 1.1776x over previous
#include <cuda_runtime.h>
#include <cuda_fp16.h>
#include <math.h>
#include <stdint.h>

#define B_  4
#define L_  2048
#define D_  1024
#define H_  16
#define DH  64
#define M_  (B_*L_)        /* 8192 */
#define NEG 1e7f

// -------------------- scratch (all half) --------------------
__device__ __half g_qpe[M_*D_];
__device__ __half g_kpe[M_*D_];
__device__ __half g_vr [M_*D_];
__device__ __half g_Qh[M_*D_];    // [B,H,L,DH]  (Q pre-scaled by 0.125)
__device__ __half g_Kh[M_*D_];
__device__ __half g_Vh[M_*D_];
__device__ __half g_attn[M_*D_];  // [B,L,D]
__device__ __half g_Wt[4*D_*D_];  // transposed weights [N][K]

// -------------------- helpers --------------------
__device__ __forceinline__ void mma16(float* c, const unsigned* a, const unsigned* b){
    asm volatile("mma.sync.aligned.m16n8k16.row.col.f32.f16.f16.f32 "
        "{%0,%1,%2,%3}, {%4,%5,%6,%7}, {%8,%9}, {%0,%1,%2,%3};"
        : "+f"(c[0]),"+f"(c[1]),"+f"(c[2]),"+f"(c[3])
        : "r"(a[0]),"r"(a[1]),"r"(a[2]),"r"(a[3]),"r"(b[0]),"r"(b[1]));
}
__device__ __forceinline__ void ldsm_x4(unsigned* r, uint32_t a){
    asm volatile("ldmatrix.sync.aligned.m8n8.x4.shared.b16 {%0,%1,%2,%3}, [%4];"
        : "=r"(r[0]),"=r"(r[1]),"=r"(r[2]),"=r"(r[3]) : "r"(a));
}
__device__ __forceinline__ void ldsm_x4t(unsigned* r, uint32_t a){
    asm volatile("ldmatrix.sync.aligned.m8n8.x4.trans.shared.b16 {%0,%1,%2,%3}, [%4];"
        : "=r"(r[0]),"=r"(r[1]),"=r"(r[2]),"=r"(r[3]) : "r"(a));
}
__device__ __forceinline__ uint32_t smem_u32(const void* p){
    uint32_t a; asm("{ .reg .u64 t; cvta.to.shared.u64 t, %1; cvt.u32.u64 %0, t; }"
                    : "=r"(a) : "l"(p)); return a;
}

// -------------------- PE add (fp32 math -> half) --------------------
__global__ void pe_add_kernel(const float* __restrict__ q, const float* __restrict__ k,
                              const float* __restrict__ v) {
    int i = blockIdx.x * blockDim.x + threadIdx.x;
    const int NF = D_ / 2;
    if (i >= M_ * NF) return;
    int row = i / NF;
    int f   = i - row * NF;
    int l   = row & (L_ - 1);
    const float kC = 9.210340371976184f / 512.0f;
    float ang = (float)l * expf(-(float)f * kC);
    float s, c;
    sincosf(ang, &s, &c);
    int base = row * D_ + 2 * f;
    *(half2*)&g_qpe[base] = __floats2half2_rn(q[base] + s, q[base+1] + c);
    *(half2*)&g_kpe[base] = __floats2half2_rn(k[base] + s, k[base+1] + c);
    *(half2*)&g_vr[base]  = __floats2half2_rn(v[base],     v[base+1]);
}

// -------------------- weight transpose -> half [N][K] --------------------
__global__ void transpose_w4(const float* __restrict__ W0, const float* __restrict__ W1,
                             const float* __restrict__ W2, const float* __restrict__ W3){
    __shared__ float t[32][33];
    const float* W = (blockIdx.z==0)?W0:(blockIdx.z==1)?W1:(blockIdx.z==2)?W2:W3;
    __half* O = g_Wt + (size_t)blockIdx.z * D_ * D_;
    int x0 = blockIdx.x*32, y0 = blockIdx.y*32;
    int tx = threadIdx.x, ty0 = threadIdx.y;   // (32, 8)
#pragma unroll
    for (int i=0;i<4;i++){ int ty=ty0+i*8; t[ty][tx] = W[(size_t)(y0+ty)*D_ + x0+tx]; }
    __syncthreads();
#pragma unroll
    for (int i=0;i<2;i++){
        int kk = ty0 + i*8;
        half2 h = __floats2half2_rn(t[2*kk][tx], t[2*kk+1][tx]);
        *(half2*)&O[(size_t)(x0+tx)*D_ + y0 + 2*kk] = h;
    }
}

// -------------------- fp16 GEMM v5: 4 warps, warp tile 64x64 --------------------
// Block 128x128, BK=32, 2-stage smem (32KB). smem row = 32 halves (64B, 4 chunks);
// chunk c of row r at r*64 + 16*(c ^ ((r>>1)&3)).
#define GS 16384
#define G_SMEM (2*GS)

template<int HEADLAYOUT>
__global__ void __launch_bounds__(128, 2)
gemm_h2(const __half* __restrict__ A, const __half* __restrict__ Wt,
        const float* __restrict__ bias, float oscale, void* __restrict__ Cv){
    extern __shared__ __align__(128) char smem[];
    uint32_t sb = smem_u32(smem);
    int tid=threadIdx.x, lane=tid&31;
    int warp=tid>>5, wm=warp>>1, wn=warp&1;
    int bm=blockIdx.y*128, bn=blockIdx.x*128;

    const __half* Ab = A  + (size_t)bm * D_;
    const __half* Bb = Wt + (size_t)bn * D_;

    float acc[4][8][4];
#pragma unroll
    for(int i=0;i<4;i++)
#pragma unroll
      for(int j=0;j<8;j++)
#pragma unroll
        for(int r=0;r<4;r++) acc[i][j][r]=0.f;

    // producer: thread -> (row pr+32*it, chunk pc)
    int pr = tid>>2, pc = tid&3;
    uint32_t stoff[4];
#pragma unroll
    for(int it=0;it<4;it++){
        int r = pr + 32*it;
        stoff[it] = r*64 + 16*(pc ^ ((r>>1)&3));
    }

    // fragment addressing
    int l7=lane&7, g8=(lane>>3)&1, g16=lane>>4;
    uint32_t aRow[4]; int aSwz[4];
#pragma unroll
    for(int mt=0;mt<4;mt++){
        int r = wm*64 + mt*16 + l7 + g8*8;
        aRow[mt] = r*64; aSwz[mt] = (r>>1)&3;
    }
    uint32_t bRow[4]; int bSwz[4];
#pragma unroll
    for(int ntp=0;ntp<4;ntp++){
        int n = wn*64 + ntp*16 + l7 + g16*8;
        bRow[ntp] = 8192u + n*64; bSwz[ntp] = (n>>1)&3;
    }

    uint4 pa[4], pb[4];
    auto ldg=[&](int ch){
#pragma unroll
        for(int it=0;it<4;it++){
            int r = pr + 32*it;
            pa[it] = *(const uint4*)(Ab + (size_t)r*D_ + ch*32 + pc*8);
            pb[it] = *(const uint4*)(Bb + (size_t)r*D_ + ch*32 + pc*8);
        }
    };
    auto sts=[&](int s){
        char* d = smem + s*GS;
#pragma unroll
        for(int it=0;it<4;it++){
            *(uint4*)(d + stoff[it]) = pa[it];
            *(uint4*)(d + 8192 + stoff[it]) = pb[it];
        }
    };

    ldg(0); sts(0); __syncthreads();

    for(int ch=0; ch<32; ch++){
        uint32_t so = sb + (ch&1)*GS;
        if(ch<31) ldg(ch+1);
#pragma unroll
        for(int ks=0;ks<2;ks++){
            unsigned bf[4][4];
#pragma unroll
            for(int ntp=0;ntp<4;ntp++)
                ldsm_x4(bf[ntp], so + bRow[ntp] + 16*((2*ks+g8)^bSwz[ntp]));
#pragma unroll
            for(int mt=0;mt<4;mt++){
                unsigned af[4];
                ldsm_x4(af, so + aRow[mt] + 16*((2*ks+g16)^aSwz[mt]));
#pragma unroll
                for(int ntp=0;ntp<4;ntp++){
                    mma16(acc[mt][2*ntp+0], af, &bf[ntp][0]);
                    mma16(acc[mt][2*ntp+1], af, &bf[ntp][2]);
                }
            }
        }
        if(ch<31){ sts((ch+1)&1); __syncthreads(); }
    }

    // epilogue
#pragma unroll
    for(int mt=0;mt<4;mt++){
        int r0 = bm + wm*64 + mt*16 + (lane>>2);
#pragma unroll
        for(int hf=0;hf<2;hf++){
            int m = r0 + hf*8;
            int bidx = m>>11, l = m&(L_-1);
#pragma unroll
            for(int nt=0;nt<8;nt++){
                int n = bn + wn*64 + nt*8 + 2*(lane&3);
                float2 bb = *(const float2*)&bias[n];
                float v0 = (acc[mt][nt][hf*2+0] + bb.x) * oscale;
                float v1 = (acc[mt][nt][hf*2+1] + bb.y) * oscale;
                if(HEADLAYOUT){
                    int h=n>>6, dd=n&63;
                    *(half2*)&((__half*)Cv)[(size_t)((bidx*H_+h)*L_+l)*DH + dd] =
                        __floats2half2_rn(v0, v1);
                } else {
                    float2 ov = make_float2(v0, v1);
                    *(float2*)&((float*)Cv)[(size_t)m*D_ + n] = ov;
                }
            }
        }
    }
}

// -------------------- fp16 flash attention (paired x4 frags) --------------------
// 128-row Q tiles, 64-key K/V tiles, 8 warps (16 rows each).
// smem rows: 64 halves = 128B; 16B chunk c of row r at r*128 + 16*(c ^ (r&7)).
#define AQ 0
#define AK 16384
#define AV 24576
#define AP 32768            /* per-warp 16x64 halves: warp*2048 */
#define APAD 49152
#define ATTN_SMEM (APAD + 256)

__global__ void __launch_bounds__(256, 2)
attn_h(const unsigned char* __restrict__ pad, __half* __restrict__ outp){
    extern __shared__ __align__(128) char smem[];
    uint32_t sb = smem_u32(smem);
    float* spad = (float*)(smem + APAD);

    int tid=threadIdx.x, lane=tid&31, warp=tid>>5;
    int qt=blockIdx.x, bh=blockIdx.y;
    int b=bh>>4, h=bh&15;
    const __half* Q = g_Qh + (size_t)bh*L_*DH;
    const __half* K = g_Kh + (size_t)bh*L_*DH;
    const __half* V = g_Vh + (size_t)bh*L_*DH;

    // load Q tile: 128 rows x 8 chunks
#pragma unroll
    for(int t=0;t<4;t++){
        int idx=t*256+tid;
        int r=idx>>3, c=idx&7;
        uint4 u = *(const uint4*)(Q + (size_t)(qt*128+r)*DH + c*8);
        *(uint4*)(smem + AQ + r*128 + 16*(c ^ (r&7))) = u;
    }

    int l7=lane&7, g8=(lane>>3)&1, g16=lane>>4;
    // Q a-frag
    int rqa = warp*16 + l7 + g8*8;
    uint32_t qOff = AQ + rqa*128;  int qSwz = rqa&7;
    // K pair b-frags: rows ntp*16 + l7 + g16*8, chunk 2ks+g8
    uint32_t kOff[4]; int kSwz[4];
#pragma unroll
    for(int ntp=0;ntp<4;ntp++){
        int n = ntp*16 + l7 + g16*8;
        kOff[ntp] = AK + n*128; kSwz[ntp] = n&7;
    }
    // P a-frag
    int rpa = l7 + g8*8;
    uint32_t pOff = AP + warp*2048 + rpa*128;  int pSwz = rpa&7;
    // V trans pair: row ks*16 + l7 + g8*8, chunk 2ntp+g16
    // P store
    int rq0 = lane>>2;
    int pc4 = 4*(lane&3);
    uint32_t pst0 = AP + warp*2048 + rq0*128;
    uint32_t pst1 = pst0 + 8*128;
    int pstSwz = rq0&7;

    float m_[2]={-1e30f,-1e30f}, l_[2]={0.f,0.f};
    float o[8][4];
#pragma unroll
    for(int i=0;i<8;i++){o[i][0]=0.f;o[i][1]=0.f;o[i][2]=0.f;o[i][3]=0.f;}
    int r0g = qt*128 + warp*16 + rq0;
    int r1g = r0g + 8;

    int nkt = 2*qt+2;
    int ktFull = 2*qt;                    // tiles < ktFull need no causal check
    for(int kt=0;kt<nkt;kt++){
        __syncthreads();
#pragma unroll
        for(int t=0;t<2;t++){
            int idx=t*256+tid;
            int r=idx>>3, c=idx&7;
            uint32_t dsto = r*128 + 16*(c ^ (r&7));
            uint4 uk = *(const uint4*)(K + (size_t)(kt*64+r)*DH + c*8);
            *(uint4*)(smem + AK + dsto) = uk;
            uint4 uv = *(const uint4*)(V + (size_t)(kt*64+r)*DH + c*8);
            *(uint4*)(smem + AV + dsto) = uv;
        }
        if(tid<64) spad[tid] = pad[b*L_ + kt*64 + tid] ? NEG : 0.f;
        __syncthreads();

        // ---- S = Q K^T ----
        float s[8][4];
#pragma unroll
        for(int i=0;i<8;i++){s[i][0]=0.f;s[i][1]=0.f;s[i][2]=0.f;s[i][3]=0.f;}
#pragma unroll
        for(int ks=0;ks<4;ks++){
            unsigned af[4];
            ldsm_x4(af, sb + qOff + 16*((2*ks + g16) ^ qSwz));
#pragma unroll
            for(int ntp=0;ntp<4;ntp++){
                unsigned bf[4];
                ldsm_x4(bf, sb + kOff[ntp] + 16*((2*ks + g8) ^ kSwz[ntp]));
                mma16(s[2*ntp+0], af, &bf[0]);
                mma16(s[2*ntp+1], af, &bf[2]);
            }
        }

        // ---- mask + online softmax (Q pre-scaled) ----
        float rmax0=-1e30f, rmax1=-1e30f;
        if(kt >= ktFull){
#pragma unroll
            for(int nt=0;nt<8;nt++){
                int cl = nt*8 + 2*(lane&3);
                int c0 = kt*64 + cl, c1 = c0+1;
                float ms0=spad[cl], ms1=spad[cl+1];
                float v0=s[nt][0] - ms0; if(c0>r0g) v0-=NEG;
                float v1=s[nt][1] - ms1; if(c1>r0g) v1-=NEG;
                float v2=s[nt][2] - ms0; if(c0>r1g) v2-=NEG;
                float v3=s[nt][3] - ms1; if(c1>r1g) v3-=NEG;
                s[nt][0]=v0; s[nt][1]=v1; s[nt][2]=v2; s[nt][3]=v3;
                rmax0=fmaxf(rmax0,fmaxf(v0,v1));
                rmax1=fmaxf(rmax1,fmaxf(v2,v3));
            }
        } else {
#pragma unroll
            for(int nt=0;nt<8;nt++){
                int cl = nt*8 + 2*(lane&3);
                float ms0=spad[cl], ms1=spad[cl+1];
                float v0=s[nt][0] - ms0;
                float v1=s[nt][1] - ms1;
                float v2=s[nt][2] - ms0;
                float v3=s[nt][3] - ms1;
                s[nt][0]=v0; s[nt][1]=v1; s[nt][2]=v2; s[nt][3]=v3;
                rmax0=fmaxf(rmax0,fmaxf(v0,v1));
                rmax1=fmaxf(rmax1,fmaxf(v2,v3));
            }
        }
        rmax0=fmaxf(rmax0,__shfl_xor_sync(0xffffffffu,rmax0,1));
        rmax0=fmaxf(rmax0,__shfl_xor_sync(0xffffffffu,rmax0,2));
        rmax1=fmaxf(rmax1,__shfl_xor_sync(0xffffffffu,rmax1,1));
        rmax1=fmaxf(rmax1,__shfl_xor_sync(0xffffffffu,rmax1,2));

        float mn0=fmaxf(m_[0],rmax0), mn1=fmaxf(m_[1],rmax1);
        float corr0=__expf(m_[0]-mn0), corr1=__expf(m_[1]-mn1);
        m_[0]=mn0; m_[1]=mn1;
        float rs0=0.f, rs1=0.f;
#pragma unroll
        for(int nt=0;nt<8;nt++){
            s[nt][0]=__expf(s[nt][0]-mn0); rs0+=s[nt][0];
            s[nt][1]=__expf(s[nt][1]-mn0); rs0+=s[nt][1];
            s[nt][2]=__expf(s[nt][2]-mn1); rs1+=s[nt][2];
            s[nt][3]=__expf(s[nt][3]-mn1); rs1+=s[nt][3];
        }
        rs0+=__shfl_xor_sync(0xffffffffu,rs0,1);
        rs0+=__shfl_xor_sync(0xffffffffu,rs0,2);
        rs1+=__shfl_xor_sync(0xffffffffu,rs1,1);
        rs1+=__shfl_xor_sync(0xffffffffu,rs1,2);
        l_[0]=l_[0]*corr0+rs0; l_[1]=l_[1]*corr1+rs1;
#pragma unroll
        for(int nt=0;nt<8;nt++){
            o[nt][0]*=corr0; o[nt][1]*=corr0;
            o[nt][2]*=corr1; o[nt][3]*=corr1;
        }

        // ---- P -> warp-private smem (half2) ----
#pragma unroll
        for(int nt=0;nt<8;nt++){
            uint32_t co = 16*(nt ^ pstSwz) + pc4;
            *(half2*)(smem + pst0 + co) = __floats2half2_rn(s[nt][0], s[nt][1]);
            *(half2*)(smem + pst1 + co) = __floats2half2_rn(s[nt][2], s[nt][3]);
        }
        __syncwarp();

        // ---- O += P V ----
#pragma unroll
        for(int ks=0;ks<4;ks++){
            unsigned pf[4];
            ldsm_x4(pf, sb + pOff + 16*((2*ks + g16) ^ pSwz));
            int vr = ks*16 + l7 + g8*8;
            uint32_t vbase = AV + vr*128;
            int vSwz = vr&7;
#pragma unroll
            for(int ntp=0;ntp<4;ntp++){
                unsigned bf[4];
                ldsm_x4t(bf, sb + vbase + 16*((2*ntp + g16) ^ vSwz));
                mma16(o[2*ntp+0], pf, &bf[0]);
                mma16(o[2*ntp+1], pf, &bf[2]);
            }
        }
    }

    // ---- normalize + write half [B,L,D] ----
    float inv0=1.f/l_[0], inv1=1.f/l_[1];
#pragma unroll
    for(int nt=0;nt<8;nt++){
        int dd = nt*8 + 2*(lane&3);
        *(half2*)&outp[(size_t)(b*L_+r0g)*D_ + h*DH + dd] =
            __floats2half2_rn(o[nt][0]*inv0, o[nt][1]*inv0);
        *(half2*)&outp[(size_t)(b*L_+r1g)*D_ + h*DH + dd] =
            __floats2half2_rn(o[nt][2]*inv1, o[nt][3]*inv1);
    }
}

// -------------------- launch --------------------
extern "C" void kernel_launch(void* const* d_in, const int* in_sizes, int n_in,
                              void* d_out, int out_size) {
    const float* q  = (const float*)d_in[0];
    const float* k  = (const float*)d_in[1];
    const float* v  = (const float*)d_in[2];
    const unsigned char* pad = (const unsigned char*)d_in[3];
    const float* Wq = (const float*)d_in[4];
    const float* bq = (const float*)d_in[5];
    const float* Wk = (const float*)d_in[6];
    const float* bk = (const float*)d_in[7];
    const float* Wv = (const float*)d_in[8];
    const float* bv = (const float*)d_in[9];
    const float* Wo = (const float*)d_in[10];
    const float* bo = (const float*)d_in[11];
    float* out = (float*)d_out;

    __half *p_qpe, *p_kpe, *p_vr, *p_Qh, *p_Kh, *p_Vh, *p_attn, *p_Wt;
    cudaGetSymbolAddress((void**)&p_qpe,  g_qpe);
    cudaGetSymbolAddress((void**)&p_kpe,  g_kpe);
    cudaGetSymbolAddress((void**)&p_vr,   g_vr);
    cudaGetSymbolAddress((void**)&p_Qh,   g_Qh);
    cudaGetSymbolAddress((void**)&p_Kh,   g_Kh);
    cudaGetSymbolAddress((void**)&p_Vh,   g_Vh);
    cudaGetSymbolAddress((void**)&p_attn, g_attn);
    cudaGetSymbolAddress((void**)&p_Wt,   g_Wt);

    cudaFuncSetAttribute(attn_h, cudaFuncAttributeMaxDynamicSharedMemorySize, ATTN_SMEM);
    cudaFuncSetAttribute(gemm_h2<0>, cudaFuncAttributeMaxDynamicSharedMemorySize, G_SMEM);
    cudaFuncSetAttribute(gemm_h2<1>, cudaFuncAttributeMaxDynamicSharedMemorySize, G_SMEM);

    // 0) weight transposes -> half [N][K]
    transpose_w4<<<dim3(32,32,4), dim3(32,8)>>>(Wq, Wk, Wv, Wo);

    // 1) positional encodings -> half
    int pe_threads = M_ * (D_ / 2);
    pe_add_kernel<<<(pe_threads + 255) / 256, 256>>>(q, k, v);

    // 2) QKV projections -> head layout (half); Q pre-scaled by 1/sqrt(d_head)
    dim3 gg(D_ / 128, M_ / 128), blk(128);
    gemm_h2<1><<<gg, blk, G_SMEM>>>(p_qpe, p_Wt + 0*(size_t)D_*D_, bq, 0.125f, p_Qh);
    gemm_h2<1><<<gg, blk, G_SMEM>>>(p_kpe, p_Wt + 1*(size_t)D_*D_, bk, 1.0f,   p_Kh);
    gemm_h2<1><<<gg, blk, G_SMEM>>>(p_vr,  p_Wt + 2*(size_t)D_*D_, bv, 1.0f,   p_Vh);

    // 3) fused causal flash attention (fp16 tensor cores)
    attn_h<<<dim3(L_ / 128, B_ * H_), 256, ATTN_SMEM>>>(pad, p_attn);

    // 4) output projection -> fp32 d_out
    gemm_h2<0><<<gg, blk, G_SMEM>>>(p_attn, p_Wt + 3*(size_t)D_*D_, bo, 1.0f, out);
}

// round 7
// speedup vs baseline: 2.9739x; 1.1044x over previous
#include <cuda_runtime.h>
#include <cuda_fp16.h>
#include <math.h>
#include <stdint.h>

#define B_  4
#define L_  2048
#define D_  1024
#define H_  16
#define DH  64
#define M_  (B_*L_)        /* 8192 */
#define NEG 1e7f

// -------------------- scratch (all half) --------------------
__device__ __half g_qpe[M_*D_];
__device__ __half g_kpe[M_*D_];
__device__ __half g_vr [M_*D_];
__device__ __half g_Qh[M_*D_];    // [B,H,L,DH]  (Q pre-scaled by 0.125)
__device__ __half g_Kh[M_*D_];
__device__ __half g_Vh[M_*D_];
__device__ __half g_attn[M_*D_];  // [B,L,D]
__device__ __half g_Wt[4*D_*D_];  // transposed weights [N][K]

// -------------------- helpers --------------------
__device__ __forceinline__ void mma16(float* c, const unsigned* a, const unsigned* b){
    asm volatile("mma.sync.aligned.m16n8k16.row.col.f32.f16.f16.f32 "
        "{%0,%1,%2,%3}, {%4,%5,%6,%7}, {%8,%9}, {%0,%1,%2,%3};"
        : "+f"(c[0]),"+f"(c[1]),"+f"(c[2]),"+f"(c[3])
        : "r"(a[0]),"r"(a[1]),"r"(a[2]),"r"(a[3]),"r"(b[0]),"r"(b[1]));
}
__device__ __forceinline__ void ldsm_x4(unsigned* r, uint32_t a){
    asm volatile("ldmatrix.sync.aligned.m8n8.x4.shared.b16 {%0,%1,%2,%3}, [%4];"
        : "=r"(r[0]),"=r"(r[1]),"=r"(r[2]),"=r"(r[3]) : "r"(a));
}
__device__ __forceinline__ void ldsm_x4t(unsigned* r, uint32_t a){
    asm volatile("ldmatrix.sync.aligned.m8n8.x4.trans.shared.b16 {%0,%1,%2,%3}, [%4];"
        : "=r"(r[0]),"=r"(r[1]),"=r"(r[2]),"=r"(r[3]) : "r"(a));
}
__device__ __forceinline__ uint32_t smem_u32(const void* p){
    uint32_t a; asm("{ .reg .u64 t; cvta.to.shared.u64 t, %1; cvt.u32.u64 %0, t; }"
                    : "=r"(a) : "l"(p)); return a;
}
__device__ __forceinline__ void cp16(uint32_t dst, const void* src){
    asm volatile("cp.async.cg.shared.global [%0], [%1], 16;" :: "r"(dst), "l"(src));
}
#define CP_COMMIT() asm volatile("cp.async.commit_group;" ::: "memory")
#define CP_WAIT1()  asm volatile("cp.async.wait_group 1;" ::: "memory")
#define CP_WAIT0()  asm volatile("cp.async.wait_group 0;" ::: "memory")

// -------------------- PE add (fp32 math -> half) --------------------
__global__ void pe_add_kernel(const float* __restrict__ q, const float* __restrict__ k,
                              const float* __restrict__ v) {
    int i = blockIdx.x * blockDim.x + threadIdx.x;
    const int NF = D_ / 2;
    if (i >= M_ * NF) return;
    int row = i / NF;
    int f   = i - row * NF;
    int l   = row & (L_ - 1);
    const float kC = 9.210340371976184f / 512.0f;
    float ang = (float)l * expf(-(float)f * kC);
    float s, c;
    sincosf(ang, &s, &c);
    int base = row * D_ + 2 * f;
    *(half2*)&g_qpe[base] = __floats2half2_rn(q[base] + s, q[base+1] + c);
    *(half2*)&g_kpe[base] = __floats2half2_rn(k[base] + s, k[base+1] + c);
    *(half2*)&g_vr[base]  = __floats2half2_rn(v[base],     v[base+1]);
}

// -------------------- weight transpose -> half [N][K] --------------------
__global__ void transpose_w4(const float* __restrict__ W0, const float* __restrict__ W1,
                             const float* __restrict__ W2, const float* __restrict__ W3){
    __shared__ float t[32][33];
    const float* W = (blockIdx.z==0)?W0:(blockIdx.z==1)?W1:(blockIdx.z==2)?W2:W3;
    __half* O = g_Wt + (size_t)blockIdx.z * D_ * D_;
    int x0 = blockIdx.x*32, y0 = blockIdx.y*32;
    int tx = threadIdx.x, ty0 = threadIdx.y;   // (32, 8)
#pragma unroll
    for (int i=0;i<4;i++){ int ty=ty0+i*8; t[ty][tx] = W[(size_t)(y0+ty)*D_ + x0+tx]; }
    __syncthreads();
#pragma unroll
    for (int i=0;i<2;i++){
        int kk = ty0 + i*8;
        half2 h = __floats2half2_rn(t[2*kk][tx], t[2*kk+1][tx]);
        *(half2*)&O[(size_t)(x0+tx)*D_ + y0 + 2*kk] = h;
    }
}

// -------------------- fp16 GEMM v6: cp.async 3-stage, 4 warps 64x64 --------------
// Block 128x128, BK=32. smem row = 32 halves (4 chunks); chunk c of row r at
// r*64 + 16*(c ^ ((r>>1)&3)).  Stage = 16KB (A 8K + B 8K), 3 stages = 48KB.
#define GS 16384
#define G_SMEM (3*GS)

template<int HEADLAYOUT>
__global__ void __launch_bounds__(128, 2)
gemm_h3(const __half* __restrict__ A, const __half* __restrict__ Wt,
        const float* __restrict__ bias, float oscale, void* __restrict__ Cv){
    extern __shared__ __align__(128) char smem[];
    uint32_t sb = smem_u32(smem);
    int tid=threadIdx.x, lane=tid&31;
    int warp=tid>>5, wm=warp>>1, wn=warp&1;
    int bm=blockIdx.y*128, bn=blockIdx.x*128;

    const __half* Ab = A  + (size_t)bm * D_;
    const __half* Bb = Wt + (size_t)bn * D_;

    float acc[4][8][4];
#pragma unroll
    for(int i=0;i<4;i++)
#pragma unroll
      for(int j=0;j<8;j++)
#pragma unroll
        for(int r=0;r<4;r++) acc[i][j][r]=0.f;

    // producer: thread -> rows pr+32*it, chunk pc
    int pr = tid>>2, pc = tid&3;
    uint32_t stoff[4];
#pragma unroll
    for(int it=0;it<4;it++){
        int r = pr + 32*it;
        stoff[it] = r*64 + 16*(pc ^ ((r>>1)&3));
    }

    // fragment addressing
    int l7=lane&7, g8=(lane>>3)&1, g16=lane>>4;
    uint32_t aRow[4]; int aSwz[4];
#pragma unroll
    for(int mt=0;mt<4;mt++){
        int r = wm*64 + mt*16 + l7 + g8*8;
        aRow[mt] = r*64; aSwz[mt] = (r>>1)&3;
    }
    uint32_t bRow[4]; int bSwz[4];
#pragma unroll
    for(int ntp=0;ntp<4;ntp++){
        int n = wn*64 + ntp*16 + l7 + g16*8;
        bRow[ntp] = 8192u + n*64; bSwz[ntp] = (n>>1)&3;
    }

    auto issue=[&](int ch){
        int s = ch % 3;
        uint32_t da = sb + s*GS;
#pragma unroll
        for(int it=0;it<4;it++){
            int r = pr + 32*it;
            cp16(da + stoff[it],         Ab + (size_t)r*D_ + ch*32 + pc*8);
            cp16(da + 8192 + stoff[it],  Bb + (size_t)r*D_ + ch*32 + pc*8);
        }
        CP_COMMIT();
    };

    issue(0); issue(1);

    for(int ch=0; ch<32; ch++){
        if(ch<31) CP_WAIT1(); else CP_WAIT0();
        __syncthreads();
        if(ch+2<32) issue(ch+2);
        uint32_t so = sb + (ch%3)*GS;
#pragma unroll
        for(int ks=0;ks<2;ks++){
            unsigned bf[4][4];
#pragma unroll
            for(int ntp=0;ntp<4;ntp++)
                ldsm_x4(bf[ntp], so + bRow[ntp] + 16*((2*ks+g8)^bSwz[ntp]));
#pragma unroll
            for(int mt=0;mt<4;mt++){
                unsigned af[4];
                ldsm_x4(af, so + aRow[mt] + 16*((2*ks+g16)^aSwz[mt]));
#pragma unroll
                for(int ntp=0;ntp<4;ntp++){
                    mma16(acc[mt][2*ntp+0], af, &bf[ntp][0]);
                    mma16(acc[mt][2*ntp+1], af, &bf[ntp][2]);
                }
            }
        }
    }

    // epilogue
#pragma unroll
    for(int mt=0;mt<4;mt++){
        int r0 = bm + wm*64 + mt*16 + (lane>>2);
#pragma unroll
        for(int hf=0;hf<2;hf++){
            int m = r0 + hf*8;
            int bidx = m>>11, l = m&(L_-1);
#pragma unroll
            for(int nt=0;nt<8;nt++){
                int n = bn + wn*64 + nt*8 + 2*(lane&3);
                float2 bb = *(const float2*)&bias[n];
                float v0 = (acc[mt][nt][hf*2+0] + bb.x) * oscale;
                float v1 = (acc[mt][nt][hf*2+1] + bb.y) * oscale;
                if(HEADLAYOUT){
                    int h=n>>6, dd=n&63;
                    *(half2*)&((__half*)Cv)[(size_t)((bidx*H_+h)*L_+l)*DH + dd] =
                        __floats2half2_rn(v0, v1);
                } else {
                    float2 ov = make_float2(v0, v1);
                    *(float2*)&((float*)Cv)[(size_t)m*D_ + n] = ov;
                }
            }
        }
    }
}

// -------------------- fp16 flash attention: cp.async double-buffered K/V ---------
// 128-row Q tiles, 64-key K/V tiles, 8 warps (16 rows each).
// smem rows: 64 halves = 128B; 16B chunk c of row r at r*128 + 16*(c ^ (r&7)).
#define AQ 0                 /* 16KB */
#define AK 16384             /* 2 x 8KB */
#define AV 32768             /* 2 x 8KB */
#define AP 49152             /* per-warp 16x64 halves: warp*2048, 16KB */
#define APAD 65536
#define ATTN_SMEM (APAD + 256)

__global__ void __launch_bounds__(256, 2)
attn_h(const unsigned char* __restrict__ pad, __half* __restrict__ outp){
    extern __shared__ __align__(128) char smem[];
    uint32_t sb = smem_u32(smem);
    float* spad = (float*)(smem + APAD);

    int tid=threadIdx.x, lane=tid&31, warp=tid>>5;
    int qt=blockIdx.x, bh=blockIdx.y;
    int b=bh>>4, h=bh&15;
    const __half* Q = g_Qh + (size_t)bh*L_*DH;
    const __half* K = g_Kh + (size_t)bh*L_*DH;
    const __half* V = g_Vh + (size_t)bh*L_*DH;

    // async load Q tile: 128 rows x 8 chunks
#pragma unroll
    for(int t=0;t<4;t++){
        int idx=t*256+tid;
        int r=idx>>3, c=idx&7;
        cp16(sb + AQ + r*128 + 16*(c ^ (r&7)),
             Q + (size_t)(qt*128+r)*DH + c*8);
    }
    CP_COMMIT();

    auto issueKV=[&](int kt){
        uint32_t buf = (kt&1)*8192u;
#pragma unroll
        for(int t=0;t<2;t++){
            int idx=t*256+tid;
            int r=idx>>3, c=idx&7;
            uint32_t off = r*128 + 16*(c ^ (r&7));
            cp16(sb + AK + buf + off, K + (size_t)(kt*64+r)*DH + c*8);
            cp16(sb + AV + buf + off, V + (size_t)(kt*64+r)*DH + c*8);
        }
        CP_COMMIT();
    };
    issueKV(0);

    int l7=lane&7, g8=(lane>>3)&1, g16=lane>>4;
    int rqa = warp*16 + l7 + g8*8;
    uint32_t qOff = AQ + rqa*128;  int qSwz = rqa&7;
    uint32_t kOff[4]; int kSwz[4];
#pragma unroll
    for(int ntp=0;ntp<4;ntp++){
        int n = ntp*16 + l7 + g16*8;
        kOff[ntp] = AK + n*128; kSwz[ntp] = n&7;
    }
    int rpa = l7 + g8*8;
    uint32_t pOff = AP + warp*2048 + rpa*128;  int pSwz = rpa&7;
    int rq0 = lane>>2;
    int pc4 = 4*(lane&3);
    uint32_t pst0 = AP + warp*2048 + rq0*128;
    uint32_t pst1 = pst0 + 8*128;
    int pstSwz = rq0&7;
    int vRow[4];
#pragma unroll
    for(int ks=0;ks<4;ks++) vRow[ks] = ks*16 + l7 + g8*8;

    float m_[2]={-1e30f,-1e30f}, l_[2]={0.f,0.f};
    float o[8][4];
#pragma unroll
    for(int i=0;i<8;i++){o[i][0]=0.f;o[i][1]=0.f;o[i][2]=0.f;o[i][3]=0.f;}
    int r0g = qt*128 + warp*16 + rq0;
    int r1g = r0g + 8;

    int nkt = 2*qt+2;
    int ktFull = 2*qt;
    for(int kt=0;kt<nkt;kt++){
        uint32_t buf = (kt&1)*8192u;
        __syncthreads();                 // all warps done with buffer (kt+1)&1
        if(kt+1<nkt){ issueKV(kt+1); CP_WAIT1(); }
        else        { CP_WAIT0(); }
        if(tid<64) spad[tid] = pad[b*L_ + kt*64 + tid] ? NEG : 0.f;
        __syncthreads();                 // KV(kt) + spad visible

        // ---- S = Q K^T ----
        float s[8][4];
#pragma unroll
        for(int i=0;i<8;i++){s[i][0]=0.f;s[i][1]=0.f;s[i][2]=0.f;s[i][3]=0.f;}
#pragma unroll
        for(int ks=0;ks<4;ks++){
            unsigned af[4];
            ldsm_x4(af, sb + qOff + 16*((2*ks + g16) ^ qSwz));
#pragma unroll
            for(int ntp=0;ntp<4;ntp++){
                unsigned bf[4];
                ldsm_x4(bf, sb + kOff[ntp] + buf + 16*((2*ks + g8) ^ kSwz[ntp]));
                mma16(s[2*ntp+0], af, &bf[0]);
                mma16(s[2*ntp+1], af, &bf[2]);
            }
        }

        // ---- mask + online softmax (Q pre-scaled) ----
        float rmax0=-1e30f, rmax1=-1e30f;
        if(kt >= ktFull){
#pragma unroll
            for(int nt=0;nt<8;nt++){
                int cl = nt*8 + 2*(lane&3);
                int c0 = kt*64 + cl, c1 = c0+1;
                float ms0=spad[cl], ms1=spad[cl+1];
                float v0=s[nt][0] - ms0; if(c0>r0g) v0-=NEG;
                float v1=s[nt][1] - ms1; if(c1>r0g) v1-=NEG;
                float v2=s[nt][2] - ms0; if(c0>r1g) v2-=NEG;
                float v3=s[nt][3] - ms1; if(c1>r1g) v3-=NEG;
                s[nt][0]=v0; s[nt][1]=v1; s[nt][2]=v2; s[nt][3]=v3;
                rmax0=fmaxf(rmax0,fmaxf(v0,v1));
                rmax1=fmaxf(rmax1,fmaxf(v2,v3));
            }
        } else {
#pragma unroll
            for(int nt=0;nt<8;nt++){
                int cl = nt*8 + 2*(lane&3);
                float ms0=spad[cl], ms1=spad[cl+1];
                float v0=s[nt][0] - ms0;
                float v1=s[nt][1] - ms1;
                float v2=s[nt][2] - ms0;
                float v3=s[nt][3] - ms1;
                s[nt][0]=v0; s[nt][1]=v1; s[nt][2]=v2; s[nt][3]=v3;
                rmax0=fmaxf(rmax0,fmaxf(v0,v1));
                rmax1=fmaxf(rmax1,fmaxf(v2,v3));
            }
        }
        rmax0=fmaxf(rmax0,__shfl_xor_sync(0xffffffffu,rmax0,1));
        rmax0=fmaxf(rmax0,__shfl_xor_sync(0xffffffffu,rmax0,2));
        rmax1=fmaxf(rmax1,__shfl_xor_sync(0xffffffffu,rmax1,1));
        rmax1=fmaxf(rmax1,__shfl_xor_sync(0xffffffffu,rmax1,2));

        float mn0=fmaxf(m_[0],rmax0), mn1=fmaxf(m_[1],rmax1);
        float corr0=__expf(m_[0]-mn0), corr1=__expf(m_[1]-mn1);
        m_[0]=mn0; m_[1]=mn1;
        float rs0=0.f, rs1=0.f;
#pragma unroll
        for(int nt=0;nt<8;nt++){
            s[nt][0]=__expf(s[nt][0]-mn0); rs0+=s[nt][0];
            s[nt][1]=__expf(s[nt][1]-mn0); rs0+=s[nt][1];
            s[nt][2]=__expf(s[nt][2]-mn1); rs1+=s[nt][2];
            s[nt][3]=__expf(s[nt][3]-mn1); rs1+=s[nt][3];
        }
        rs0+=__shfl_xor_sync(0xffffffffu,rs0,1);
        rs0+=__shfl_xor_sync(0xffffffffu,rs0,2);
        rs1+=__shfl_xor_sync(0xffffffffu,rs1,1);
        rs1+=__shfl_xor_sync(0xffffffffu,rs1,2);
        l_[0]=l_[0]*corr0+rs0; l_[1]=l_[1]*corr1+rs1;
#pragma unroll
        for(int nt=0;nt<8;nt++){
            o[nt][0]*=corr0; o[nt][1]*=corr0;
            o[nt][2]*=corr1; o[nt][3]*=corr1;
        }

        // ---- P -> warp-private smem (half2) ----
#pragma unroll
        for(int nt=0;nt<8;nt++){
            uint32_t co = 16*(nt ^ pstSwz) + pc4;
            *(half2*)(smem + pst0 + co) = __floats2half2_rn(s[nt][0], s[nt][1]);
            *(half2*)(smem + pst1 + co) = __floats2half2_rn(s[nt][2], s[nt][3]);
        }
        __syncwarp();

        // ---- O += P V ----
#pragma unroll
        for(int ks=0;ks<4;ks++){
            unsigned pf[4];
            ldsm_x4(pf, sb + pOff + 16*((2*ks + g16) ^ pSwz));
            uint32_t vbase = AV + buf + vRow[ks]*128;
            int vSwz = vRow[ks]&7;
#pragma unroll
            for(int ntp=0;ntp<4;ntp++){
                unsigned bf[4];
                ldsm_x4t(bf, sb + vbase + 16*((2*ntp + g16) ^ vSwz));
                mma16(o[2*ntp+0], pf, &bf[0]);
                mma16(o[2*ntp+1], pf, &bf[2]);
            }
        }
    }

    // ---- normalize + write half [B,L,D] ----
    float inv0=1.f/l_[0], inv1=1.f/l_[1];
#pragma unroll
    for(int nt=0;nt<8;nt++){
        int dd = nt*8 + 2*(lane&3);
        *(half2*)&outp[(size_t)(b*L_+r0g)*D_ + h*DH + dd] =
            __floats2half2_rn(o[nt][0]*inv0, o[nt][1]*inv0);
        *(half2*)&outp[(size_t)(b*L_+r1g)*D_ + h*DH + dd] =
            __floats2half2_rn(o[nt][2]*inv1, o[nt][3]*inv1);
    }
}

// -------------------- launch --------------------
extern "C" void kernel_launch(void* const* d_in, const int* in_sizes, int n_in,
                              void* d_out, int out_size) {
    const float* q  = (const float*)d_in[0];
    const float* k  = (const float*)d_in[1];
    const float* v  = (const float*)d_in[2];
    const unsigned char* pad = (const unsigned char*)d_in[3];
    const float* Wq = (const float*)d_in[4];
    const float* bq = (const float*)d_in[5];
    const float* Wk = (const float*)d_in[6];
    const float* bk = (const float*)d_in[7];
    const float* Wv = (const float*)d_in[8];
    const float* bv = (const float*)d_in[9];
    const float* Wo = (const float*)d_in[10];
    const float* bo = (const float*)d_in[11];
    float* out = (float*)d_out;

    __half *p_qpe, *p_kpe, *p_vr, *p_Qh, *p_Kh, *p_Vh, *p_attn, *p_Wt;
    cudaGetSymbolAddress((void**)&p_qpe,  g_qpe);
    cudaGetSymbolAddress((void**)&p_kpe,  g_kpe);
    cudaGetSymbolAddress((void**)&p_vr,   g_vr);
    cudaGetSymbolAddress((void**)&p_Qh,   g_Qh);
    cudaGetSymbolAddress((void**)&p_Kh,   g_Kh);
    cudaGetSymbolAddress((void**)&p_Vh,   g_Vh);
    cudaGetSymbolAddress((void**)&p_attn, g_attn);
    cudaGetSymbolAddress((void**)&p_Wt,   g_Wt);

    cudaFuncSetAttribute(attn_h, cudaFuncAttributeMaxDynamicSharedMemorySize, ATTN_SMEM);
    cudaFuncSetAttribute(gemm_h3<0>, cudaFuncAttributeMaxDynamicSharedMemorySize, G_SMEM);
    cudaFuncSetAttribute(gemm_h3<1>, cudaFuncAttributeMaxDynamicSharedMemorySize, G_SMEM);

    // 0) weight transposes -> half [N][K]
    transpose_w4<<<dim3(32,32,4), dim3(32,8)>>>(Wq, Wk, Wv, Wo);

    // 1) positional encodings -> half
    int pe_threads = M_ * (D_ / 2);
    pe_add_kernel<<<(pe_threads + 255) / 256, 256>>>(q, k, v);

    // 2) QKV projections -> head layout (half); Q pre-scaled by 1/sqrt(d_head)
    dim3 gg(D_ / 128, M_ / 128), blk(128);
    gemm_h3<1><<<gg, blk, G_SMEM>>>(p_qpe, p_Wt + 0*(size_t)D_*D_, bq, 0.125f, p_Qh);
    gemm_h3<1><<<gg, blk, G_SMEM>>>(p_kpe, p_Wt + 1*(size_t)D_*D_, bk, 1.0f,   p_Kh);
    gemm_h3<1><<<gg, blk, G_SMEM>>>(p_vr,  p_Wt + 2*(size_t)D_*D_, bv, 1.0f,   p_Vh);

    // 3) fused causal flash attention (fp16 tensor cores, cp.async)
    attn_h<<<dim3(L_ / 128, B_ * H_), 256, ATTN_SMEM>>>(pad, p_attn);

    // 4) output projection -> fp32 d_out
    gemm_h3<0><<<gg, blk, G_SMEM>>>(p_attn, p_Wt + 3*(size_t)D_*D_, bo, 1.0f, out);
}

// round 8
// speedup vs baseline: 3.0178x; 1.0148x over previous
#include <cuda_runtime.h>
#include <cuda_fp16.h>
#include <math.h>
#include <stdint.h>

#define B_  4
#define L_  2048
#define D_  1024
#define H_  16
#define DH  64
#define M_  (B_*L_)        /* 8192 */
#define NEG 1e7f

// -------------------- scratch (all half) --------------------
__device__ __half g_qpe[M_*D_];
__device__ __half g_kpe[M_*D_];
__device__ __half g_vr [M_*D_];
__device__ __half g_Qh[M_*D_];    // [B,H,L,DH]  (Q pre-scaled by 0.125*log2e)
__device__ __half g_Kh[M_*D_];
__device__ __half g_Vh[M_*D_];
__device__ __half g_attn[M_*D_];  // [B,L,D]
__device__ __half g_Wt[4*D_*D_];  // transposed weights [N][K]

// -------------------- helpers --------------------
__device__ __forceinline__ void mma16(float* c, const unsigned* a, const unsigned* b){
    asm volatile("mma.sync.aligned.m16n8k16.row.col.f32.f16.f16.f32 "
        "{%0,%1,%2,%3}, {%4,%5,%6,%7}, {%8,%9}, {%0,%1,%2,%3};"
        : "+f"(c[0]),"+f"(c[1]),"+f"(c[2]),"+f"(c[3])
        : "r"(a[0]),"r"(a[1]),"r"(a[2]),"r"(a[3]),"r"(b[0]),"r"(b[1]));
}
__device__ __forceinline__ void ldsm_x4(unsigned* r, uint32_t a){
    asm volatile("ldmatrix.sync.aligned.m8n8.x4.shared.b16 {%0,%1,%2,%3}, [%4];"
        : "=r"(r[0]),"=r"(r[1]),"=r"(r[2]),"=r"(r[3]) : "r"(a));
}
__device__ __forceinline__ void ldsm_x4t(unsigned* r, uint32_t a){
    asm volatile("ldmatrix.sync.aligned.m8n8.x4.trans.shared.b16 {%0,%1,%2,%3}, [%4];"
        : "=r"(r[0]),"=r"(r[1]),"=r"(r[2]),"=r"(r[3]) : "r"(a));
}
__device__ __forceinline__ uint32_t smem_u32(const void* p){
    uint32_t a; asm("{ .reg .u64 t; cvta.to.shared.u64 t, %1; cvt.u32.u64 %0, t; }"
                    : "=r"(a) : "l"(p)); return a;
}
__device__ __forceinline__ void cp16(uint32_t dst, const void* src){
    asm volatile("cp.async.cg.shared.global [%0], [%1], 16;" :: "r"(dst), "l"(src));
}
#define CP_COMMIT() asm volatile("cp.async.commit_group;" ::: "memory")
#define CP_WAIT2()  asm volatile("cp.async.wait_group 2;" ::: "memory")
#define CP_WAIT1()  asm volatile("cp.async.wait_group 1;" ::: "memory")
#define CP_WAIT0()  asm volatile("cp.async.wait_group 0;" ::: "memory")
__device__ __forceinline__ float fexp2(float x){
    float y; asm("ex2.approx.ftz.f32 %0, %1;" : "=f"(y) : "f"(x)); return y;
}

// -------------------- PE add (fp32 math -> half) --------------------
__global__ void pe_add_kernel(const float* __restrict__ q, const float* __restrict__ k,
                              const float* __restrict__ v) {
    int i = blockIdx.x * blockDim.x + threadIdx.x;
    const int NF = D_ / 2;
    if (i >= M_ * NF) return;
    int row = i / NF;
    int f   = i - row * NF;
    int l   = row & (L_ - 1);
    const float kC = 9.210340371976184f / 512.0f;
    float ang = (float)l * expf(-(float)f * kC);
    float s, c;
    sincosf(ang, &s, &c);
    int base = row * D_ + 2 * f;
    *(half2*)&g_qpe[base] = __floats2half2_rn(q[base] + s, q[base+1] + c);
    *(half2*)&g_kpe[base] = __floats2half2_rn(k[base] + s, k[base+1] + c);
    *(half2*)&g_vr[base]  = __floats2half2_rn(v[base],     v[base+1]);
}

// -------------------- weight transpose -> half [N][K] --------------------
__global__ void transpose_w4(const float* __restrict__ W0, const float* __restrict__ W1,
                             const float* __restrict__ W2, const float* __restrict__ W3){
    __shared__ float t[32][33];
    const float* W = (blockIdx.z==0)?W0:(blockIdx.z==1)?W1:(blockIdx.z==2)?W2:W3;
    __half* O = g_Wt + (size_t)blockIdx.z * D_ * D_;
    int x0 = blockIdx.x*32, y0 = blockIdx.y*32;
    int tx = threadIdx.x, ty0 = threadIdx.y;   // (32, 8)
#pragma unroll
    for (int i=0;i<4;i++){ int ty=ty0+i*8; t[ty][tx] = W[(size_t)(y0+ty)*D_ + x0+tx]; }
    __syncthreads();
#pragma unroll
    for (int i=0;i<2;i++){
        int kk = ty0 + i*8;
        half2 h = __floats2half2_rn(t[2*kk][tx], t[2*kk+1][tx]);
        *(half2*)&O[(size_t)(x0+tx)*D_ + y0 + 2*kk] = h;
    }
}

// -------------------- fp16 GEMM v7: cp.async 4-stage, 4 warps 64x64 --------------
// Block 128x128, BK=32. smem row = 32 halves (4 chunks); chunk c of row r at
// r*64 + 16*(c ^ ((r>>1)&3)).  Stage = 16KB (A 8K + B 8K), 4 stages = 64KB.
#define GS 16384
#define G_SMEM (4*GS)

template<int HEADLAYOUT>
__global__ void __launch_bounds__(128, 2)
gemm_h4(const __half* __restrict__ A, const __half* __restrict__ Wt,
        const float* __restrict__ bias, float oscale, void* __restrict__ Cv){
    extern __shared__ __align__(128) char smem[];
    uint32_t sb = smem_u32(smem);
    int tid=threadIdx.x, lane=tid&31;
    int warp=tid>>5, wm=warp>>1, wn=warp&1;
    int bm=blockIdx.y*128, bn=blockIdx.x*128;

    const __half* Ab = A  + (size_t)bm * D_;
    const __half* Bb = Wt + (size_t)bn * D_;

    float acc[4][8][4];
#pragma unroll
    for(int i=0;i<4;i++)
#pragma unroll
      for(int j=0;j<8;j++)
#pragma unroll
        for(int r=0;r<4;r++) acc[i][j][r]=0.f;

    // producer: thread -> rows pr+32*it, chunk pc
    int pr = tid>>2, pc = tid&3;
    uint32_t stoff[4];
#pragma unroll
    for(int it=0;it<4;it++){
        int r = pr + 32*it;
        stoff[it] = r*64 + 16*(pc ^ ((r>>1)&3));
    }

    // fragment addressing
    int l7=lane&7, g8=(lane>>3)&1, g16=lane>>4;
    uint32_t aRow[4]; int aSwz[4];
#pragma unroll
    for(int mt=0;mt<4;mt++){
        int r = wm*64 + mt*16 + l7 + g8*8;
        aRow[mt] = r*64; aSwz[mt] = (r>>1)&3;
    }
    uint32_t bRow[4]; int bSwz[4];
#pragma unroll
    for(int ntp=0;ntp<4;ntp++){
        int n = wn*64 + ntp*16 + l7 + g16*8;
        bRow[ntp] = 8192u + n*64; bSwz[ntp] = (n>>1)&3;
    }

    auto issue=[&](int ch){
        int s = ch & 3;
        uint32_t da = sb + s*GS;
#pragma unroll
        for(int it=0;it<4;it++){
            int r = pr + 32*it;
            cp16(da + stoff[it],         Ab + (size_t)r*D_ + ch*32 + pc*8);
            cp16(da + 8192 + stoff[it],  Bb + (size_t)r*D_ + ch*32 + pc*8);
        }
        CP_COMMIT();
    };

    issue(0); issue(1); issue(2);

    for(int ch=0; ch<32; ch++){
        if(ch<30) CP_WAIT2(); else if(ch==30) CP_WAIT1(); else CP_WAIT0();
        __syncthreads();
        if(ch+3<32) issue(ch+3);
        uint32_t so = sb + (ch&3)*GS;
#pragma unroll
        for(int ks=0;ks<2;ks++){
            unsigned bf[4][4];
#pragma unroll
            for(int ntp=0;ntp<4;ntp++)
                ldsm_x4(bf[ntp], so + bRow[ntp] + 16*((2*ks+g8)^bSwz[ntp]));
#pragma unroll
            for(int mt=0;mt<4;mt++){
                unsigned af[4];
                ldsm_x4(af, so + aRow[mt] + 16*((2*ks+g16)^aSwz[mt]));
#pragma unroll
                for(int ntp=0;ntp<4;ntp++){
                    mma16(acc[mt][2*ntp+0], af, &bf[ntp][0]);
                    mma16(acc[mt][2*ntp+1], af, &bf[ntp][2]);
                }
            }
        }
    }

    // epilogue
#pragma unroll
    for(int mt=0;mt<4;mt++){
        int r0 = bm + wm*64 + mt*16 + (lane>>2);
#pragma unroll
        for(int hf=0;hf<2;hf++){
            int m = r0 + hf*8;
            int bidx = m>>11, l = m&(L_-1);
#pragma unroll
            for(int nt=0;nt<8;nt++){
                int n = bn + wn*64 + nt*8 + 2*(lane&3);
                float2 bb = *(const float2*)&bias[n];
                float v0 = (acc[mt][nt][hf*2+0] + bb.x) * oscale;
                float v1 = (acc[mt][nt][hf*2+1] + bb.y) * oscale;
                if(HEADLAYOUT){
                    int h=n>>6, dd=n&63;
                    *(half2*)&((__half*)Cv)[(size_t)((bidx*H_+h)*L_+l)*DH + dd] =
                        __floats2half2_rn(v0, v1);
                } else {
                    float2 ov = make_float2(v0, v1);
                    *(float2*)&((float*)Cv)[(size_t)m*D_ + n] = ov;
                }
            }
        }
    }
}

// -------------------- fp16 flash attention: log2-domain softmax, h2exp2 ----------
// Scores arrive in log2 units (Q pre-scaled by 0.125*log2e). 128-row Q tiles,
// 64-key K/V tiles, 8 warps. smem rows: 64 halves = 128B; chunk c of row r at
// r*128 + 16*(c ^ (r&7)).
#define AQ 0                 /* 16KB */
#define AK 16384             /* 2 x 8KB */
#define AV 32768             /* 2 x 8KB */
#define AP 49152             /* per-warp 16x64 halves: warp*2048, 16KB */
#define APAD 65536
#define ATTN_SMEM (APAD + 256)

__global__ void __launch_bounds__(256, 2)
attn_h(const unsigned char* __restrict__ pad, __half* __restrict__ outp){
    extern __shared__ __align__(128) char smem[];
    uint32_t sb = smem_u32(smem);
    float* spad = (float*)(smem + APAD);

    int tid=threadIdx.x, lane=tid&31, warp=tid>>5;
    int qt=blockIdx.x, bh=blockIdx.y;
    int b=bh>>4, h=bh&15;
    const __half* Q = g_Qh + (size_t)bh*L_*DH;
    const __half* K = g_Kh + (size_t)bh*L_*DH;
    const __half* V = g_Vh + (size_t)bh*L_*DH;

    // async load Q tile: 128 rows x 8 chunks
#pragma unroll
    for(int t=0;t<4;t++){
        int idx=t*256+tid;
        int r=idx>>3, c=idx&7;
        cp16(sb + AQ + r*128 + 16*(c ^ (r&7)),
             Q + (size_t)(qt*128+r)*DH + c*8);
    }
    CP_COMMIT();

    auto issueKV=[&](int kt){
        uint32_t buf = (kt&1)*8192u;
#pragma unroll
        for(int t=0;t<2;t++){
            int idx=t*256+tid;
            int r=idx>>3, c=idx&7;
            uint32_t off = r*128 + 16*(c ^ (r&7));
            cp16(sb + AK + buf + off, K + (size_t)(kt*64+r)*DH + c*8);
            cp16(sb + AV + buf + off, V + (size_t)(kt*64+r)*DH + c*8);
        }
        CP_COMMIT();
    };
    issueKV(0);

    int l7=lane&7, g8=(lane>>3)&1, g16=lane>>4;
    int rqa = warp*16 + l7 + g8*8;
    uint32_t qOff = AQ + rqa*128;  int qSwz = rqa&7;
    uint32_t kOff[4]; int kSwz[4];
#pragma unroll
    for(int ntp=0;ntp<4;ntp++){
        int n = ntp*16 + l7 + g16*8;
        kOff[ntp] = AK + n*128; kSwz[ntp] = n&7;
    }
    int rpa = l7 + g8*8;
    uint32_t pOff = AP + warp*2048 + rpa*128;  int pSwz = rpa&7;
    int rq0 = lane>>2;
    int pc4 = 4*(lane&3);
    uint32_t pst0 = AP + warp*2048 + rq0*128;
    uint32_t pst1 = pst0 + 8*128;
    int pstSwz = rq0&7;
    int vRow[4];
#pragma unroll
    for(int ks=0;ks<4;ks++) vRow[ks] = ks*16 + l7 + g8*8;

    float m_[2]={-1e30f,-1e30f}, l_[2]={0.f,0.f};
    float o[8][4];
#pragma unroll
    for(int i=0;i<8;i++){o[i][0]=0.f;o[i][1]=0.f;o[i][2]=0.f;o[i][3]=0.f;}
    int r0g = qt*128 + warp*16 + rq0;
    int r1g = r0g + 8;

    int nkt = 2*qt+2;
    int ktFull = 2*qt;
    for(int kt=0;kt<nkt;kt++){
        uint32_t buf = (kt&1)*8192u;
        __syncthreads();                 // all warps done with buffer (kt+1)&1
        if(kt+1<nkt){ issueKV(kt+1); CP_WAIT1(); }
        else        { CP_WAIT0(); }
        if(tid<64) spad[tid] = pad[b*L_ + kt*64 + tid] ? NEG : 0.f;
        __syncthreads();                 // KV(kt) + spad visible

        // ---- S = Q K^T (log2 units) ----
        float s[8][4];
#pragma unroll
        for(int i=0;i<8;i++){s[i][0]=0.f;s[i][1]=0.f;s[i][2]=0.f;s[i][3]=0.f;}
#pragma unroll
        for(int ks=0;ks<4;ks++){
            unsigned af[4];
            ldsm_x4(af, sb + qOff + 16*((2*ks + g16) ^ qSwz));
#pragma unroll
            for(int ntp=0;ntp<4;ntp++){
                unsigned bf[4];
                ldsm_x4(bf, sb + kOff[ntp] + buf + 16*((2*ks + g8) ^ kSwz[ntp]));
                mma16(s[2*ntp+0], af, &bf[0]);
                mma16(s[2*ntp+1], af, &bf[2]);
            }
        }

        // ---- mask + row max (log2 domain) ----
        float rmax0=-1e30f, rmax1=-1e30f;
        if(kt >= ktFull){
#pragma unroll
            for(int nt=0;nt<8;nt++){
                int cl = nt*8 + 2*(lane&3);
                int c0 = kt*64 + cl, c1 = c0+1;
                float ms0=spad[cl], ms1=spad[cl+1];
                float v0=s[nt][0] - ms0; if(c0>r0g) v0-=NEG;
                float v1=s[nt][1] - ms1; if(c1>r0g) v1-=NEG;
                float v2=s[nt][2] - ms0; if(c0>r1g) v2-=NEG;
                float v3=s[nt][3] - ms1; if(c1>r1g) v3-=NEG;
                s[nt][0]=v0; s[nt][1]=v1; s[nt][2]=v2; s[nt][3]=v3;
                rmax0=fmaxf(rmax0,fmaxf(v0,v1));
                rmax1=fmaxf(rmax1,fmaxf(v2,v3));
            }
        } else {
#pragma unroll
            for(int nt=0;nt<8;nt++){
                int cl = nt*8 + 2*(lane&3);
                float ms0=spad[cl], ms1=spad[cl+1];
                float v0=s[nt][0] - ms0;
                float v1=s[nt][1] - ms1;
                float v2=s[nt][2] - ms0;
                float v3=s[nt][3] - ms1;
                s[nt][0]=v0; s[nt][1]=v1; s[nt][2]=v2; s[nt][3]=v3;
                rmax0=fmaxf(rmax0,fmaxf(v0,v1));
                rmax1=fmaxf(rmax1,fmaxf(v2,v3));
            }
        }
        rmax0=fmaxf(rmax0,__shfl_xor_sync(0xffffffffu,rmax0,1));
        rmax0=fmaxf(rmax0,__shfl_xor_sync(0xffffffffu,rmax0,2));
        rmax1=fmaxf(rmax1,__shfl_xor_sync(0xffffffffu,rmax1,1));
        rmax1=fmaxf(rmax1,__shfl_xor_sync(0xffffffffu,rmax1,2));

        float mn0=fmaxf(m_[0],rmax0), mn1=fmaxf(m_[1],rmax1);
        float corr0=fexp2(m_[0]-mn0), corr1=fexp2(m_[1]-mn1);
        m_[0]=mn0; m_[1]=mn1;

        // ---- exp2 in f16x2, store P, accumulate row sums in fp32 ----
        float rs0=0.f, rs1=0.f;
#pragma unroll
        for(int nt=0;nt<8;nt++){
            half2 e01 = h2exp2(__floats2half2_rn(s[nt][0]-mn0, s[nt][1]-mn0));
            half2 e23 = h2exp2(__floats2half2_rn(s[nt][2]-mn1, s[nt][3]-mn1));
            uint32_t co = 16*(nt ^ pstSwz) + pc4;
            *(half2*)(smem + pst0 + co) = e01;
            *(half2*)(smem + pst1 + co) = e23;
            float2 f01 = __half22float2(e01);
            float2 f23 = __half22float2(e23);
            rs0 += f01.x + f01.y;
            rs1 += f23.x + f23.y;
        }
        rs0+=__shfl_xor_sync(0xffffffffu,rs0,1);
        rs0+=__shfl_xor_sync(0xffffffffu,rs0,2);
        rs1+=__shfl_xor_sync(0xffffffffu,rs1,1);
        rs1+=__shfl_xor_sync(0xffffffffu,rs1,2);
        l_[0]=l_[0]*corr0+rs0; l_[1]=l_[1]*corr1+rs1;
#pragma unroll
        for(int nt=0;nt<8;nt++){
            o[nt][0]*=corr0; o[nt][1]*=corr0;
            o[nt][2]*=corr1; o[nt][3]*=corr1;
        }
        __syncwarp();

        // ---- O += P V ----
#pragma unroll
        for(int ks=0;ks<4;ks++){
            unsigned pf[4];
            ldsm_x4(pf, sb + pOff + 16*((2*ks + g16) ^ pSwz));
            uint32_t vbase = AV + buf + vRow[ks]*128;
            int vSwz = vRow[ks]&7;
#pragma unroll
            for(int ntp=0;ntp<4;ntp++){
                unsigned bf[4];
                ldsm_x4t(bf, sb + vbase + 16*((2*ntp + g16) ^ vSwz));
                mma16(o[2*ntp+0], pf, &bf[0]);
                mma16(o[2*ntp+1], pf, &bf[2]);
            }
        }
    }

    // ---- normalize + write half [B,L,D] ----
    float inv0=1.f/l_[0], inv1=1.f/l_[1];
#pragma unroll
    for(int nt=0;nt<8;nt++){
        int dd = nt*8 + 2*(lane&3);
        *(half2*)&outp[(size_t)(b*L_+r0g)*D_ + h*DH + dd] =
            __floats2half2_rn(o[nt][0]*inv0, o[nt][1]*inv0);
        *(half2*)&outp[(size_t)(b*L_+r1g)*D_ + h*DH + dd] =
            __floats2half2_rn(o[nt][2]*inv1, o[nt][3]*inv1);
    }
}

// -------------------- launch --------------------
extern "C" void kernel_launch(void* const* d_in, const int* in_sizes, int n_in,
                              void* d_out, int out_size) {
    const float* q  = (const float*)d_in[0];
    const float* k  = (const float*)d_in[1];
    const float* v  = (const float*)d_in[2];
    const unsigned char* pad = (const unsigned char*)d_in[3];
    const float* Wq = (const float*)d_in[4];
    const float* bq = (const float*)d_in[5];
    const float* Wk = (const float*)d_in[6];
    const float* bk = (const float*)d_in[7];
    const float* Wv = (const float*)d_in[8];
    const float* bv = (const float*)d_in[9];
    const float* Wo = (const float*)d_in[10];
    const float* bo = (const float*)d_in[11];
    float* out = (float*)d_out;

    __half *p_qpe, *p_kpe, *p_vr, *p_Qh, *p_Kh, *p_Vh, *p_attn, *p_Wt;
    cudaGetSymbolAddress((void**)&p_qpe,  g_qpe);
    cudaGetSymbolAddress((void**)&p_kpe,  g_kpe);
    cudaGetSymbolAddress((void**)&p_vr,   g_vr);
    cudaGetSymbolAddress((void**)&p_Qh,   g_Qh);
    cudaGetSymbolAddress((void**)&p_Kh,   g_Kh);
    cudaGetSymbolAddress((void**)&p_Vh,   g_Vh);
    cudaGetSymbolAddress((void**)&p_attn, g_attn);
    cudaGetSymbolAddress((void**)&p_Wt,   g_Wt);

    cudaFuncSetAttribute(attn_h, cudaFuncAttributeMaxDynamicSharedMemorySize, ATTN_SMEM);
    cudaFuncSetAttribute(gemm_h4<0>, cudaFuncAttributeMaxDynamicSharedMemorySize, G_SMEM);
    cudaFuncSetAttribute(gemm_h4<1>, cudaFuncAttributeMaxDynamicSharedMemorySize, G_SMEM);

    // 0) weight transposes -> half [N][K]
    transpose_w4<<<dim3(32,32,4), dim3(32,8)>>>(Wq, Wk, Wv, Wo);

    // 1) positional encodings -> half
    int pe_threads = M_ * (D_ / 2);
    pe_add_kernel<<<(pe_threads + 255) / 256, 256>>>(q, k, v);

    // 2) QKV projections -> head layout (half); Q pre-scaled by 0.125*log2e
    dim3 gg(D_ / 128, M_ / 128), blk(128);
    gemm_h4<1><<<gg, blk, G_SMEM>>>(p_qpe, p_Wt + 0*(size_t)D_*D_, bq, 0.18033688f, p_Qh);
    gemm_h4<1><<<gg, blk, G_SMEM>>>(p_kpe, p_Wt + 1*(size_t)D_*D_, bk, 1.0f,        p_Kh);
    gemm_h4<1><<<gg, blk, G_SMEM>>>(p_vr,  p_Wt + 2*(size_t)D_*D_, bv, 1.0f,        p_Vh);

    // 3) fused causal flash attention (fp16 tensor cores, log2-domain softmax)
    attn_h<<<dim3(L_ / 128, B_ * H_), 256, ATTN_SMEM>>>(pad, p_attn);

    // 4) output projection -> fp32 d_out
    gemm_h4<0><<<gg, blk, G_SMEM>>>(p_attn, p_Wt + 3*(size_t)D_*D_, bo, 1.0f, out);
}

// round 9
// speedup vs baseline: 3.2684x; 1.0830x over previous
#include <cuda_runtime.h>
#include <cuda_fp16.h>
#include <math.h>
#include <stdint.h>

#define B_  4
#define L_  2048
#define D_  1024
#define H_  16
#define DH  64
#define M_  (B_*L_)        /* 8192 */
#define NEG 1e7f

// -------------------- scratch (all half) --------------------
__device__ __half g_qpe[M_*D_];
__device__ __half g_kpe[M_*D_];
__device__ __half g_vr [M_*D_];
__device__ __half g_Qh[M_*D_];    // [B,H,L,DH]  (Q pre-scaled by 0.125*log2e)
__device__ __half g_Kh[M_*D_];
__device__ __half g_Vh[M_*D_];
__device__ __half g_attn[M_*D_];  // [B,L,D]
__device__ __half g_Wt[4*D_*D_];  // transposed weights [N][K]

// -------------------- helpers --------------------
__device__ __forceinline__ void mma16(float* c, const unsigned* a, const unsigned* b){
    asm volatile("mma.sync.aligned.m16n8k16.row.col.f32.f16.f16.f32 "
        "{%0,%1,%2,%3}, {%4,%5,%6,%7}, {%8,%9}, {%0,%1,%2,%3};"
        : "+f"(c[0]),"+f"(c[1]),"+f"(c[2]),"+f"(c[3])
        : "r"(a[0]),"r"(a[1]),"r"(a[2]),"r"(a[3]),"r"(b[0]),"r"(b[1]));
}
__device__ __forceinline__ void ldsm_x4(unsigned* r, uint32_t a){
    asm volatile("ldmatrix.sync.aligned.m8n8.x4.shared.b16 {%0,%1,%2,%3}, [%4];"
        : "=r"(r[0]),"=r"(r[1]),"=r"(r[2]),"=r"(r[3]) : "r"(a));
}
__device__ __forceinline__ void ldsm_x4t(unsigned* r, uint32_t a){
    asm volatile("ldmatrix.sync.aligned.m8n8.x4.trans.shared.b16 {%0,%1,%2,%3}, [%4];"
        : "=r"(r[0]),"=r"(r[1]),"=r"(r[2]),"=r"(r[3]) : "r"(a));
}
__device__ __forceinline__ uint32_t smem_u32(const void* p){
    uint32_t a; asm("{ .reg .u64 t; cvta.to.shared.u64 t, %1; cvt.u32.u64 %0, t; }"
                    : "=r"(a) : "l"(p)); return a;
}
__device__ __forceinline__ void cp16(uint32_t dst, const void* src){
    asm volatile("cp.async.cg.shared.global [%0], [%1], 16;" :: "r"(dst), "l"(src));
}
#define CP_COMMIT() asm volatile("cp.async.commit_group;" ::: "memory")
#define CP_WAIT1()  asm volatile("cp.async.wait_group 1;" ::: "memory")
#define CP_WAIT0()  asm volatile("cp.async.wait_group 0;" ::: "memory")
__device__ __forceinline__ float fexp2(float x){
    float y; asm("ex2.approx.ftz.f32 %0, %1;" : "=f"(y) : "f"(x)); return y;
}

// -------------------- PE add (fp32 math -> half) --------------------
__global__ void pe_add_kernel(const float* __restrict__ q, const float* __restrict__ k,
                              const float* __restrict__ v) {
    int i = blockIdx.x * blockDim.x + threadIdx.x;
    const int NF = D_ / 2;
    if (i >= M_ * NF) return;
    int row = i / NF;
    int f   = i - row * NF;
    int l   = row & (L_ - 1);
    const float kC = 9.210340371976184f / 512.0f;
    float ang = (float)l * expf(-(float)f * kC);
    float s, c;
    sincosf(ang, &s, &c);
    int base = row * D_ + 2 * f;
    *(half2*)&g_qpe[base] = __floats2half2_rn(q[base] + s, q[base+1] + c);
    *(half2*)&g_kpe[base] = __floats2half2_rn(k[base] + s, k[base+1] + c);
    *(half2*)&g_vr[base]  = __floats2half2_rn(v[base],     v[base+1]);
}

// -------------------- weight transpose -> half [N][K] --------------------
__global__ void transpose_w4(const float* __restrict__ W0, const float* __restrict__ W1,
                             const float* __restrict__ W2, const float* __restrict__ W3){
    __shared__ float t[32][33];
    const float* W = (blockIdx.z==0)?W0:(blockIdx.z==1)?W1:(blockIdx.z==2)?W2:W3;
    __half* O = g_Wt + (size_t)blockIdx.z * D_ * D_;
    int x0 = blockIdx.x*32, y0 = blockIdx.y*32;
    int tx = threadIdx.x, ty0 = threadIdx.y;   // (32, 8)
#pragma unroll
    for (int i=0;i<4;i++){ int ty=ty0+i*8; t[ty][tx] = W[(size_t)(y0+ty)*D_ + x0+tx]; }
    __syncthreads();
#pragma unroll
    for (int i=0;i<2;i++){
        int kk = ty0 + i*8;
        half2 h = __floats2half2_rn(t[2*kk][tx], t[2*kk+1][tx]);
        *(half2*)&O[(size_t)(x0+tx)*D_ + y0 + 2*kk] = h;
    }
}

// -------------------- fp16 GEMM v8: BK=64, 3-stage cp.async, optional QKV fusion --
// Block 128x128, BK=64. smem row = 64 halves (128B, 8 chunks); chunk c of row r
// at r*128 + 16*(c ^ (r&7)). Stage = 32KB (A 16K + B 16K), 3 stages = 96KB.
#define GS 32768
#define G_SMEM (3*GS)

template<int QKV>
__global__ void __launch_bounds__(128, 2)
gemm_h5(const __half* __restrict__ A0, const __half* __restrict__ A1,
        const __half* __restrict__ A2, const __half* __restrict__ WtBase,
        const float* __restrict__ b0, const float* __restrict__ b1,
        const float* __restrict__ b2,
        void* O0, void* O1, void* O2, float qs){
    extern __shared__ __align__(128) char smem[];
    uint32_t sb = smem_u32(smem);
    int z = QKV ? blockIdx.z : 0;
    const __half* A    = (z==0)?A0:(z==1)?A1:A2;
    const __half* Wt   = WtBase + (size_t)(QKV ? z : 3) * D_ * D_;
    const float*  bias = (z==0)?b0:(z==1)?b1:b2;
    void* Cv           = (z==0)?O0:(z==1)?O1:O2;
    float oscale       = (QKV && z==0) ? qs : 1.f;

    int tid=threadIdx.x, lane=tid&31;
    int warp=tid>>5, wm=warp>>1, wn=warp&1;
    int bm=blockIdx.y*128, bn=blockIdx.x*128;

    const __half* Ab = A  + (size_t)bm * D_;
    const __half* Bb = Wt + (size_t)bn * D_;

    float acc[4][8][4];
#pragma unroll
    for(int i=0;i<4;i++)
#pragma unroll
      for(int j=0;j<8;j++)
#pragma unroll
        for(int r=0;r<4;r++) acc[i][j][r]=0.f;

    // producer: 8 iters, idx = it*128+tid -> row idx>>3, chunk idx&7
    int prr = tid>>3, prc = tid&7;
    uint32_t stoff[8]; int prow[8];
#pragma unroll
    for(int it=0;it<8;it++){
        int r = prr + 16*it;
        prow[it] = r;
        stoff[it] = r*128 + 16*(prc ^ (r&7));
    }

    // fragment addressing (128B rows, 8 chunks)
    int l7=lane&7, g8=(lane>>3)&1, g16=lane>>4;
    uint32_t aRow[4]; int aSwz[4];
#pragma unroll
    for(int mt=0;mt<4;mt++){
        int r = wm*64 + mt*16 + l7 + g8*8;
        aRow[mt] = r*128; aSwz[mt] = r&7;
    }
    uint32_t bRow[4]; int bSwz[4];
#pragma unroll
    for(int ntp=0;ntp<4;ntp++){
        int n = wn*64 + ntp*16 + l7 + g16*8;
        bRow[ntp] = 16384u + n*128; bSwz[ntp] = n&7;
    }

    auto issue=[&](int ch){
        int s = ch % 3;
        uint32_t da = sb + s*GS;
#pragma unroll
        for(int it=0;it<8;it++){
            cp16(da + stoff[it],          Ab + (size_t)prow[it]*D_ + ch*64 + prc*8);
            cp16(da + 16384 + stoff[it],  Bb + (size_t)prow[it]*D_ + ch*64 + prc*8);
        }
        CP_COMMIT();
    };

    issue(0); issue(1);

    for(int ch=0; ch<16; ch++){
        if(ch<15) CP_WAIT1(); else CP_WAIT0();
        __syncthreads();
        if(ch+2<16) issue(ch+2);
        uint32_t so = sb + (ch%3)*GS;
#pragma unroll
        for(int ks=0;ks<4;ks++){
            unsigned bf[4][4];
#pragma unroll
            for(int ntp=0;ntp<4;ntp++)
                ldsm_x4(bf[ntp], so + bRow[ntp] + 16*((2*ks+g8)^bSwz[ntp]));
#pragma unroll
            for(int mt=0;mt<4;mt++){
                unsigned af[4];
                ldsm_x4(af, so + aRow[mt] + 16*((2*ks+g16)^aSwz[mt]));
#pragma unroll
                for(int ntp=0;ntp<4;ntp++){
                    mma16(acc[mt][2*ntp+0], af, &bf[ntp][0]);
                    mma16(acc[mt][2*ntp+1], af, &bf[ntp][2]);
                }
            }
        }
    }

    // epilogue
#pragma unroll
    for(int mt=0;mt<4;mt++){
        int r0 = bm + wm*64 + mt*16 + (lane>>2);
#pragma unroll
        for(int hf=0;hf<2;hf++){
            int m = r0 + hf*8;
            int bidx = m>>11, l = m&(L_-1);
#pragma unroll
            for(int nt=0;nt<8;nt++){
                int n = bn + wn*64 + nt*8 + 2*(lane&3);
                float2 bb = *(const float2*)&bias[n];
                float v0 = (acc[mt][nt][hf*2+0] + bb.x) * oscale;
                float v1 = (acc[mt][nt][hf*2+1] + bb.y) * oscale;
                if(QKV){
                    int h=n>>6, dd=n&63;
                    *(half2*)&((__half*)Cv)[(size_t)((bidx*H_+h)*L_+l)*DH + dd] =
                        __floats2half2_rn(v0, v1);
                } else {
                    float2 ov = make_float2(v0, v1);
                    *(float2*)&((float*)Cv)[(size_t)m*D_ + n] = ov;
                }
            }
        }
    }
}

// -------------------- fp16 flash attention: 128-key buffers, 2x64 passes ---------
// Scores in log2 units (Q pre-scaled by 0.125*log2e). 128-row Q tiles,
// K/V double buffers of 128 keys each; softmax processed in two 64-key halves.
// smem rows: 64 halves = 128B; chunk c of row r at r*128 + 16*(c ^ (r&7)).
#define AQ 0                 /* 16KB */
#define AK 16384             /* 2 x 16KB */
#define AV 49152             /* 2 x 16KB */
#define AP 81920             /* per-warp 16x64 halves: warp*2048, 16KB */
#define APAD 98304           /* 128 floats */
#define ATTN_SMEM (APAD + 512)

__global__ void __launch_bounds__(256, 2)
attn_h(const unsigned char* __restrict__ pad, __half* __restrict__ outp){
    extern __shared__ __align__(128) char smem[];
    uint32_t sb = smem_u32(smem);
    float* spad = (float*)(smem + APAD);

    int tid=threadIdx.x, lane=tid&31, warp=tid>>5;
    int qt = (int)(gridDim.x - 1) - (int)blockIdx.x;   // long blocks first
    int bh=blockIdx.y;
    int b=bh>>4, h=bh&15;
    const __half* Q = g_Qh + (size_t)bh*L_*DH;
    const __half* K = g_Kh + (size_t)bh*L_*DH;
    const __half* V = g_Vh + (size_t)bh*L_*DH;

    // async load Q tile: 128 rows x 8 chunks
#pragma unroll
    for(int t=0;t<4;t++){
        int idx=t*256+tid;
        int r=idx>>3, c=idx&7;
        cp16(sb + AQ + r*128 + 16*(c ^ (r&7)),
             Q + (size_t)(qt*128+r)*DH + c*8);
    }
    CP_COMMIT();

    // load 128-key K/V tile pair into buffer kt2&1
    auto issueKV=[&](int kt2){
        uint32_t buf = (kt2&1)*16384u;
#pragma unroll
        for(int t=0;t<4;t++){
            int idx=t*256+tid;
            int r=idx>>3, c=idx&7;
            uint32_t off = r*128 + 16*(c ^ (r&7));
            cp16(sb + AK + buf + off, K + (size_t)(kt2*128+r)*DH + c*8);
            cp16(sb + AV + buf + off, V + (size_t)(kt2*128+r)*DH + c*8);
        }
        CP_COMMIT();
    };
    issueKV(0);

    int l7=lane&7, g8=(lane>>3)&1, g16=lane>>4;
    int rqa = warp*16 + l7 + g8*8;
    uint32_t qOff = AQ + rqa*128;  int qSwz = rqa&7;
    uint32_t kOff[4]; int kSwz[4];
#pragma unroll
    for(int ntp=0;ntp<4;ntp++){
        int n = ntp*16 + l7 + g16*8;
        kOff[ntp] = AK + n*128; kSwz[ntp] = n&7;
    }
    int rpa = l7 + g8*8;
    uint32_t pOff = AP + warp*2048 + rpa*128;  int pSwz = rpa&7;
    int rq0 = lane>>2;
    int pc4 = 4*(lane&3);
    uint32_t pst0 = AP + warp*2048 + rq0*128;
    uint32_t pst1 = pst0 + 8*128;
    int pstSwz = rq0&7;
    int vRow[4];
#pragma unroll
    for(int ks=0;ks<4;ks++) vRow[ks] = ks*16 + l7 + g8*8;

    float m_[2]={-1e30f,-1e30f}, l_[2]={0.f,0.f};
    float o[8][4];
#pragma unroll
    for(int i=0;i<8;i++){o[i][0]=0.f;o[i][1]=0.f;o[i][2]=0.f;o[i][3]=0.f;}
    int r0g = qt*128 + warp*16 + rq0;
    int r1g = r0g + 8;

    int nkt2 = qt+1;
    for(int kt2=0;kt2<nkt2;kt2++){
        __syncthreads();                 // all warps done with buffer (kt2+1)&1
        if(kt2+1<nkt2){ issueKV(kt2+1); CP_WAIT1(); }
        else          { CP_WAIT0(); }
        if(tid<128) spad[tid] = pad[b*L_ + kt2*128 + tid] ? NEG : 0.f;
        __syncthreads();                 // KV(kt2) + spad visible
        bool diag = (kt2 == qt);

#pragma unroll
        for(int hk=0;hk<2;hk++){
            uint32_t kvb = (kt2&1)*16384u + hk*8192u;
            const float* sp = spad + hk*64;

            // ---- S = Q K^T (log2 units) ----
            float s[8][4];
#pragma unroll
            for(int i=0;i<8;i++){s[i][0]=0.f;s[i][1]=0.f;s[i][2]=0.f;s[i][3]=0.f;}
#pragma unroll
            for(int ks=0;ks<4;ks++){
                unsigned af[4];
                ldsm_x4(af, sb + qOff + 16*((2*ks + g16) ^ qSwz));
#pragma unroll
                for(int ntp=0;ntp<4;ntp++){
                    unsigned bf[4];
                    ldsm_x4(bf, sb + kOff[ntp] + kvb + 16*((2*ks + g8) ^ kSwz[ntp]));
                    mma16(s[2*ntp+0], af, &bf[0]);
                    mma16(s[2*ntp+1], af, &bf[2]);
                }
            }

            // ---- mask + row max ----
            float rmax0=-1e30f, rmax1=-1e30f;
            if(diag){
                int cbase = kt2*128 + hk*64;
#pragma unroll
                for(int nt=0;nt<8;nt++){
                    int cl = nt*8 + 2*(lane&3);
                    int c0 = cbase + cl, c1 = c0+1;
                    float ms0=sp[cl], ms1=sp[cl+1];
                    float v0=s[nt][0] - ms0; if(c0>r0g) v0-=NEG;
                    float v1=s[nt][1] - ms1; if(c1>r0g) v1-=NEG;
                    float v2=s[nt][2] - ms0; if(c0>r1g) v2-=NEG;
                    float v3=s[nt][3] - ms1; if(c1>r1g) v3-=NEG;
                    s[nt][0]=v0; s[nt][1]=v1; s[nt][2]=v2; s[nt][3]=v3;
                    rmax0=fmaxf(rmax0,fmaxf(v0,v1));
                    rmax1=fmaxf(rmax1,fmaxf(v2,v3));
                }
            } else {
#pragma unroll
                for(int nt=0;nt<8;nt++){
                    int cl = nt*8 + 2*(lane&3);
                    float ms0=sp[cl], ms1=sp[cl+1];
                    float v0=s[nt][0] - ms0;
                    float v1=s[nt][1] - ms1;
                    float v2=s[nt][2] - ms0;
                    float v3=s[nt][3] - ms1;
                    s[nt][0]=v0; s[nt][1]=v1; s[nt][2]=v2; s[nt][3]=v3;
                    rmax0=fmaxf(rmax0,fmaxf(v0,v1));
                    rmax1=fmaxf(rmax1,fmaxf(v2,v3));
                }
            }
            rmax0=fmaxf(rmax0,__shfl_xor_sync(0xffffffffu,rmax0,1));
            rmax0=fmaxf(rmax0,__shfl_xor_sync(0xffffffffu,rmax0,2));
            rmax1=fmaxf(rmax1,__shfl_xor_sync(0xffffffffu,rmax1,1));
            rmax1=fmaxf(rmax1,__shfl_xor_sync(0xffffffffu,rmax1,2));

            float mn0=fmaxf(m_[0],rmax0), mn1=fmaxf(m_[1],rmax1);
            float corr0=fexp2(m_[0]-mn0), corr1=fexp2(m_[1]-mn1);
            m_[0]=mn0; m_[1]=mn1;

            // ---- exp2 in f16x2, store P, accumulate row sums ----
            float rs0=0.f, rs1=0.f;
#pragma unroll
            for(int nt=0;nt<8;nt++){
                half2 e01 = h2exp2(__floats2half2_rn(s[nt][0]-mn0, s[nt][1]-mn0));
                half2 e23 = h2exp2(__floats2half2_rn(s[nt][2]-mn1, s[nt][3]-mn1));
                uint32_t co = 16*(nt ^ pstSwz) + pc4;
                *(half2*)(smem + pst0 + co) = e01;
                *(half2*)(smem + pst1 + co) = e23;
                float2 f01 = __half22float2(e01);
                float2 f23 = __half22float2(e23);
                rs0 += f01.x + f01.y;
                rs1 += f23.x + f23.y;
            }
            rs0+=__shfl_xor_sync(0xffffffffu,rs0,1);
            rs0+=__shfl_xor_sync(0xffffffffu,rs0,2);
            rs1+=__shfl_xor_sync(0xffffffffu,rs1,1);
            rs1+=__shfl_xor_sync(0xffffffffu,rs1,2);
            l_[0]=l_[0]*corr0+rs0; l_[1]=l_[1]*corr1+rs1;
#pragma unroll
            for(int nt=0;nt<8;nt++){
                o[nt][0]*=corr0; o[nt][1]*=corr0;
                o[nt][2]*=corr1; o[nt][3]*=corr1;
            }
            __syncwarp();

            // ---- O += P V ----
#pragma unroll
            for(int ks=0;ks<4;ks++){
                unsigned pf[4];
                ldsm_x4(pf, sb + pOff + 16*((2*ks + g16) ^ pSwz));
                uint32_t vbase = AV + kvb + vRow[ks]*128;
                int vSwz = vRow[ks]&7;
#pragma unroll
                for(int ntp=0;ntp<4;ntp++){
                    unsigned bf[4];
                    ldsm_x4t(bf, sb + vbase + 16*((2*ntp + g16) ^ vSwz));
                    mma16(o[2*ntp+0], pf, &bf[0]);
                    mma16(o[2*ntp+1], pf, &bf[2]);
                }
            }
            __syncwarp();                 // P buffer reused next half
        }
    }

    // ---- normalize + write half [B,L,D] ----
    float inv0=1.f/l_[0], inv1=1.f/l_[1];
#pragma unroll
    for(int nt=0;nt<8;nt++){
        int dd = nt*8 + 2*(lane&3);
        *(half2*)&outp[(size_t)(b*L_+r0g)*D_ + h*DH + dd] =
            __floats2half2_rn(o[nt][0]*inv0, o[nt][1]*inv0);
        *(half2*)&outp[(size_t)(b*L_+r1g)*D_ + h*DH + dd] =
            __floats2half2_rn(o[nt][2]*inv1, o[nt][3]*inv1);
    }
}

// -------------------- launch --------------------
extern "C" void kernel_launch(void* const* d_in, const int* in_sizes, int n_in,
                              void* d_out, int out_size) {
    const float* q  = (const float*)d_in[0];
    const float* k  = (const float*)d_in[1];
    const float* v  = (const float*)d_in[2];
    const unsigned char* pad = (const unsigned char*)d_in[3];
    const float* Wq = (const float*)d_in[4];
    const float* bq = (const float*)d_in[5];
    const float* Wk = (const float*)d_in[6];
    const float* bk = (const float*)d_in[7];
    const float* Wv = (const float*)d_in[8];
    const float* bv = (const float*)d_in[9];
    const float* Wo = (const float*)d_in[10];
    const float* bo = (const float*)d_in[11];
    float* out = (float*)d_out;

    __half *p_qpe, *p_kpe, *p_vr, *p_Qh, *p_Kh, *p_Vh, *p_attn, *p_Wt;
    cudaGetSymbolAddress((void**)&p_qpe,  g_qpe);
    cudaGetSymbolAddress((void**)&p_kpe,  g_kpe);
    cudaGetSymbolAddress((void**)&p_vr,   g_vr);
    cudaGetSymbolAddress((void**)&p_Qh,   g_Qh);
    cudaGetSymbolAddress((void**)&p_Kh,   g_Kh);
    cudaGetSymbolAddress((void**)&p_Vh,   g_Vh);
    cudaGetSymbolAddress((void**)&p_attn, g_attn);
    cudaGetSymbolAddress((void**)&p_Wt,   g_Wt);

    cudaFuncSetAttribute(attn_h, cudaFuncAttributeMaxDynamicSharedMemorySize, ATTN_SMEM);
    cudaFuncSetAttribute(gemm_h5<0>, cudaFuncAttributeMaxDynamicSharedMemorySize, G_SMEM);
    cudaFuncSetAttribute(gemm_h5<1>, cudaFuncAttributeMaxDynamicSharedMemorySize, G_SMEM);

    // 0) weight transposes -> half [N][K]
    transpose_w4<<<dim3(32,32,4), dim3(32,8)>>>(Wq, Wk, Wv, Wo);

    // 1) positional encodings -> half
    int pe_threads = M_ * (D_ / 2);
    pe_add_kernel<<<(pe_threads + 255) / 256, 256>>>(q, k, v);

    // 2) fused QKV projections -> head layout (half); Q pre-scaled by 0.125*log2e
    gemm_h5<1><<<dim3(8, 64, 3), 128, G_SMEM>>>(
        p_qpe, p_kpe, p_vr, p_Wt, bq, bk, bv,
        (void*)p_Qh, (void*)p_Kh, (void*)p_Vh, 0.18033688f);

    // 3) fused causal flash attention (fp16 tensor cores, log2-domain softmax)
    attn_h<<<dim3(L_ / 128, B_ * H_), 256, ATTN_SMEM>>>(pad, p_attn);

    // 4) output projection -> fp32 d_out
    gemm_h5<0><<<dim3(8, 64, 1), 128, G_SMEM>>>(
        p_attn, nullptr, nullptr, p_Wt, bo, nullptr, nullptr,
        (void*)out, nullptr, nullptr, 1.0f);
}

// round 10
// speedup vs baseline: 3.4313x; 1.0499x over previous
#include <cuda_runtime.h>
#include <cuda_fp16.h>
#include <math.h>
#include <stdint.h>

#define B_  4
#define L_  2048
#define D_  1024
#define H_  16
#define DH  64
#define M_  (B_*L_)        /* 8192 */
#define NEG 1e7f

// -------------------- scratch (all half) --------------------
__device__ __half g_qpe[M_*D_];
__device__ __half g_kpe[M_*D_];
__device__ __half g_vr [M_*D_];
__device__ __half g_Qh[M_*D_];    // [B,H,L,DH]  (Q pre-scaled by 0.125*log2e)
__device__ __half g_Kh[M_*D_];
__device__ __half g_Vh[M_*D_];
__device__ __half g_attn[M_*D_];  // [B,L,D]
__device__ __half g_Wt[4*D_*D_];  // transposed weights [N][K]

// -------------------- helpers --------------------
__device__ __forceinline__ void mma16(float* c, const unsigned* a, const unsigned* b){
    asm volatile("mma.sync.aligned.m16n8k16.row.col.f32.f16.f16.f32 "
        "{%0,%1,%2,%3}, {%4,%5,%6,%7}, {%8,%9}, {%0,%1,%2,%3};"
        : "+f"(c[0]),"+f"(c[1]),"+f"(c[2]),"+f"(c[3])
        : "r"(a[0]),"r"(a[1]),"r"(a[2]),"r"(a[3]),"r"(b[0]),"r"(b[1]));
}
__device__ __forceinline__ void ldsm_x4(unsigned* r, uint32_t a){
    asm volatile("ldmatrix.sync.aligned.m8n8.x4.shared.b16 {%0,%1,%2,%3}, [%4];"
        : "=r"(r[0]),"=r"(r[1]),"=r"(r[2]),"=r"(r[3]) : "r"(a));
}
__device__ __forceinline__ void ldsm_x4t(unsigned* r, uint32_t a){
    asm volatile("ldmatrix.sync.aligned.m8n8.x4.trans.shared.b16 {%0,%1,%2,%3}, [%4];"
        : "=r"(r[0]),"=r"(r[1]),"=r"(r[2]),"=r"(r[3]) : "r"(a));
}
__device__ __forceinline__ uint32_t smem_u32(const void* p){
    uint32_t a; asm("{ .reg .u64 t; cvta.to.shared.u64 t, %1; cvt.u32.u64 %0, t; }"
                    : "=r"(a) : "l"(p)); return a;
}
__device__ __forceinline__ void cp16(uint32_t dst, const void* src){
    asm volatile("cp.async.cg.shared.global [%0], [%1], 16;" :: "r"(dst), "l"(src));
}
#define CP_COMMIT() asm volatile("cp.async.commit_group;" ::: "memory")
#define CP_WAIT1()  asm volatile("cp.async.wait_group 1;" ::: "memory")
#define CP_WAIT0()  asm volatile("cp.async.wait_group 0;" ::: "memory")
__device__ __forceinline__ float fexp2(float x){
    float y; asm("ex2.approx.ftz.f32 %0, %1;" : "=f"(y) : "f"(x)); return y;
}

// -------------------- PE add (fp32 math -> half) --------------------
__global__ void pe_add_kernel(const float* __restrict__ q, const float* __restrict__ k,
                              const float* __restrict__ v) {
    int i = blockIdx.x * blockDim.x + threadIdx.x;
    const int NF = D_ / 2;
    if (i >= M_ * NF) return;
    int row = i / NF;
    int f   = i - row * NF;
    int l   = row & (L_ - 1);
    const float kC = 9.210340371976184f / 512.0f;
    float ang = (float)l * expf(-(float)f * kC);
    float s, c;
    sincosf(ang, &s, &c);
    int base = row * D_ + 2 * f;
    *(half2*)&g_qpe[base] = __floats2half2_rn(q[base] + s, q[base+1] + c);
    *(half2*)&g_kpe[base] = __floats2half2_rn(k[base] + s, k[base+1] + c);
    *(half2*)&g_vr[base]  = __floats2half2_rn(v[base],     v[base+1]);
}

// -------------------- weight transpose -> half [N][K] --------------------
__global__ void transpose_w4(const float* __restrict__ W0, const float* __restrict__ W1,
                             const float* __restrict__ W2, const float* __restrict__ W3){
    __shared__ float t[32][33];
    const float* W = (blockIdx.z==0)?W0:(blockIdx.z==1)?W1:(blockIdx.z==2)?W2:W3;
    __half* O = g_Wt + (size_t)blockIdx.z * D_ * D_;
    int x0 = blockIdx.x*32, y0 = blockIdx.y*32;
    int tx = threadIdx.x, ty0 = threadIdx.y;   // (32, 8)
#pragma unroll
    for (int i=0;i<4;i++){ int ty=ty0+i*8; t[ty][tx] = W[(size_t)(y0+ty)*D_ + x0+tx]; }
    __syncthreads();
#pragma unroll
    for (int i=0;i<2;i++){
        int kk = ty0 + i*8;
        half2 h = __floats2half2_rn(t[2*kk][tx], t[2*kk+1][tx]);
        *(half2*)&O[(size_t)(x0+tx)*D_ + y0 + 2*kk] = h;
    }
}

// -------------------- fp16 GEMM v8: BK=64, 3-stage cp.async, optional QKV fusion --
// Block 128x128, BK=64. smem row = 64 halves (128B, 8 chunks); chunk c of row r
// at r*128 + 16*(c ^ (r&7)). Stage = 32KB (A 16K + B 16K), 3 stages = 96KB.
#define GS 32768
#define G_SMEM (3*GS)

template<int QKV>
__global__ void __launch_bounds__(128, 2)
gemm_h5(const __half* __restrict__ A0, const __half* __restrict__ A1,
        const __half* __restrict__ A2, const __half* __restrict__ WtBase,
        const float* __restrict__ b0, const float* __restrict__ b1,
        const float* __restrict__ b2,
        void* O0, void* O1, void* O2, float qs){
    extern __shared__ __align__(128) char smem[];
    uint32_t sb = smem_u32(smem);
    int z = QKV ? blockIdx.z : 0;
    const __half* A    = (z==0)?A0:(z==1)?A1:A2;
    const __half* Wt   = WtBase + (size_t)(QKV ? z : 3) * D_ * D_;
    const float*  bias = (z==0)?b0:(z==1)?b1:b2;
    void* Cv           = (z==0)?O0:(z==1)?O1:O2;
    float oscale       = (QKV && z==0) ? qs : 1.f;

    int tid=threadIdx.x, lane=tid&31;
    int warp=tid>>5, wm=warp>>1, wn=warp&1;
    int bm=blockIdx.y*128, bn=blockIdx.x*128;

    const __half* Ab = A  + (size_t)bm * D_;
    const __half* Bb = Wt + (size_t)bn * D_;

    float acc[4][8][4];
#pragma unroll
    for(int i=0;i<4;i++)
#pragma unroll
      for(int j=0;j<8;j++)
#pragma unroll
        for(int r=0;r<4;r++) acc[i][j][r]=0.f;

    // producer: 8 iters, idx = it*128+tid -> row idx>>3, chunk idx&7
    int prr = tid>>3, prc = tid&7;
    uint32_t stoff[8]; int prow[8];
#pragma unroll
    for(int it=0;it<8;it++){
        int r = prr + 16*it;
        prow[it] = r;
        stoff[it] = r*128 + 16*(prc ^ (r&7));
    }

    // fragment addressing (128B rows, 8 chunks)
    int l7=lane&7, g8=(lane>>3)&1, g16=lane>>4;
    uint32_t aRow[4]; int aSwz[4];
#pragma unroll
    for(int mt=0;mt<4;mt++){
        int r = wm*64 + mt*16 + l7 + g8*8;
        aRow[mt] = r*128; aSwz[mt] = r&7;
    }
    uint32_t bRow[4]; int bSwz[4];
#pragma unroll
    for(int ntp=0;ntp<4;ntp++){
        int n = wn*64 + ntp*16 + l7 + g16*8;
        bRow[ntp] = 16384u + n*128; bSwz[ntp] = n&7;
    }

    auto issue=[&](int ch){
        int s = ch % 3;
        uint32_t da = sb + s*GS;
#pragma unroll
        for(int it=0;it<8;it++){
            cp16(da + stoff[it],          Ab + (size_t)prow[it]*D_ + ch*64 + prc*8);
            cp16(da + 16384 + stoff[it],  Bb + (size_t)prow[it]*D_ + ch*64 + prc*8);
        }
        CP_COMMIT();
    };

    issue(0); issue(1);

    for(int ch=0; ch<16; ch++){
        if(ch<15) CP_WAIT1(); else CP_WAIT0();
        __syncthreads();
        if(ch+2<16) issue(ch+2);
        uint32_t so = sb + (ch%3)*GS;
#pragma unroll
        for(int ks=0;ks<4;ks++){
            unsigned bf[4][4];
#pragma unroll
            for(int ntp=0;ntp<4;ntp++)
                ldsm_x4(bf[ntp], so + bRow[ntp] + 16*((2*ks+g8)^bSwz[ntp]));
#pragma unroll
            for(int mt=0;mt<4;mt++){
                unsigned af[4];
                ldsm_x4(af, so + aRow[mt] + 16*((2*ks+g16)^aSwz[mt]));
#pragma unroll
                for(int ntp=0;ntp<4;ntp++){
                    mma16(acc[mt][2*ntp+0], af, &bf[ntp][0]);
                    mma16(acc[mt][2*ntp+1], af, &bf[ntp][2]);
                }
            }
        }
    }

    // epilogue
#pragma unroll
    for(int mt=0;mt<4;mt++){
        int r0 = bm + wm*64 + mt*16 + (lane>>2);
#pragma unroll
        for(int hf=0;hf<2;hf++){
            int m = r0 + hf*8;
            int bidx = m>>11, l = m&(L_-1);
#pragma unroll
            for(int nt=0;nt<8;nt++){
                int n = bn + wn*64 + nt*8 + 2*(lane&3);
                float2 bb = *(const float2*)&bias[n];
                float v0 = (acc[mt][nt][hf*2+0] + bb.x) * oscale;
                float v1 = (acc[mt][nt][hf*2+1] + bb.y) * oscale;
                if(QKV){
                    int h=n>>6, dd=n&63;
                    *(half2*)&((__half*)Cv)[(size_t)((bidx*H_+h)*L_+l)*DH + dd] =
                        __floats2half2_rn(v0, v1);
                } else {
                    float2 ov = make_float2(v0, v1);
                    *(float2*)&((float*)Cv)[(size_t)m*D_ + n] = ov;
                }
            }
        }
    }
}

// -------------------- fp16 flash attention: register-resident P (FA2) ------------
// Scores in log2 units (Q pre-scaled by 0.125*log2e). 128-row Q tiles,
// K/V double buffers of 128 keys; softmax in two 64-key halves. P never touches
// smem: the exp'd S fragments ARE the PV A-operand fragments.
// smem rows: 64 halves = 128B; chunk c of row r at r*128 + 16*(c ^ (r&7)).
#define AQ 0                 /* 16KB */
#define AK 16384             /* 2 x 16KB */
#define AV 49152             /* 2 x 16KB */
#define APAD 81920           /* 128 floats */
#define ATTN_SMEM (APAD + 512)

__global__ void __launch_bounds__(256, 2)
attn_h(const unsigned char* __restrict__ pad, __half* __restrict__ outp){
    extern __shared__ __align__(128) char smem[];
    uint32_t sb = smem_u32(smem);
    float* spad = (float*)(smem + APAD);

    int tid=threadIdx.x, lane=tid&31, warp=tid>>5;
    int qt = (int)(gridDim.x - 1) - (int)blockIdx.x;   // long blocks first
    int bh=blockIdx.y;
    int b=bh>>4, h=bh&15;
    const __half* Q = g_Qh + (size_t)bh*L_*DH;
    const __half* K = g_Kh + (size_t)bh*L_*DH;
    const __half* V = g_Vh + (size_t)bh*L_*DH;

    // async load Q tile: 128 rows x 8 chunks
#pragma unroll
    for(int t=0;t<4;t++){
        int idx=t*256+tid;
        int r=idx>>3, c=idx&7;
        cp16(sb + AQ + r*128 + 16*(c ^ (r&7)),
             Q + (size_t)(qt*128+r)*DH + c*8);
    }
    CP_COMMIT();

    // load 128-key K/V tile pair into buffer kt2&1
    auto issueKV=[&](int kt2){
        uint32_t buf = (kt2&1)*16384u;
#pragma unroll
        for(int t=0;t<4;t++){
            int idx=t*256+tid;
            int r=idx>>3, c=idx&7;
            uint32_t off = r*128 + 16*(c ^ (r&7));
            cp16(sb + AK + buf + off, K + (size_t)(kt2*128+r)*DH + c*8);
            cp16(sb + AV + buf + off, V + (size_t)(kt2*128+r)*DH + c*8);
        }
        CP_COMMIT();
    };
    issueKV(0);

    int l7=lane&7, g8=(lane>>3)&1, g16=lane>>4;
    int rqa = warp*16 + l7 + g8*8;
    uint32_t qOff = AQ + rqa*128;  int qSwz = rqa&7;
    uint32_t kOff[4]; int kSwz[4];
#pragma unroll
    for(int ntp=0;ntp<4;ntp++){
        int n = ntp*16 + l7 + g16*8;
        kOff[ntp] = AK + n*128; kSwz[ntp] = n&7;
    }
    int rq0 = lane>>2;
    int vRow[4];
#pragma unroll
    for(int ks=0;ks<4;ks++) vRow[ks] = ks*16 + l7 + g8*8;

    float m_[2]={-1e30f,-1e30f}, l_[2]={0.f,0.f};
    float o[8][4];
#pragma unroll
    for(int i=0;i<8;i++){o[i][0]=0.f;o[i][1]=0.f;o[i][2]=0.f;o[i][3]=0.f;}
    int r0g = qt*128 + warp*16 + rq0;
    int r1g = r0g + 8;

    int nkt2 = qt+1;
    for(int kt2=0;kt2<nkt2;kt2++){
        __syncthreads();                 // all warps done with buffer (kt2+1)&1
        if(kt2+1<nkt2){ issueKV(kt2+1); CP_WAIT1(); }
        else          { CP_WAIT0(); }
        if(tid<128) spad[tid] = pad[b*L_ + kt2*128 + tid] ? NEG : 0.f;
        __syncthreads();                 // KV(kt2) + spad visible
        bool diag = (kt2 == qt);

#pragma unroll
        for(int hk=0;hk<2;hk++){
            uint32_t kvb = (kt2&1)*16384u + hk*8192u;
            const float* sp = spad + hk*64;

            // ---- S = Q K^T (log2 units) ----
            float s[8][4];
#pragma unroll
            for(int i=0;i<8;i++){s[i][0]=0.f;s[i][1]=0.f;s[i][2]=0.f;s[i][3]=0.f;}
#pragma unroll
            for(int ks=0;ks<4;ks++){
                unsigned af[4];
                ldsm_x4(af, sb + qOff + 16*((2*ks + g16) ^ qSwz));
#pragma unroll
                for(int ntp=0;ntp<4;ntp++){
                    unsigned bf[4];
                    ldsm_x4(bf, sb + kOff[ntp] + kvb + 16*((2*ks + g8) ^ kSwz[ntp]));
                    mma16(s[2*ntp+0], af, &bf[0]);
                    mma16(s[2*ntp+1], af, &bf[2]);
                }
            }

            // ---- mask + row max ----
            float rmax0=-1e30f, rmax1=-1e30f;
            if(diag){
                int cbase = kt2*128 + hk*64;
#pragma unroll
                for(int nt=0;nt<8;nt++){
                    int cl = nt*8 + 2*(lane&3);
                    int c0 = cbase + cl, c1 = c0+1;
                    float ms0=sp[cl], ms1=sp[cl+1];
                    float v0=s[nt][0] - ms0; if(c0>r0g) v0-=NEG;
                    float v1=s[nt][1] - ms1; if(c1>r0g) v1-=NEG;
                    float v2=s[nt][2] - ms0; if(c0>r1g) v2-=NEG;
                    float v3=s[nt][3] - ms1; if(c1>r1g) v3-=NEG;
                    s[nt][0]=v0; s[nt][1]=v1; s[nt][2]=v2; s[nt][3]=v3;
                    rmax0=fmaxf(rmax0,fmaxf(v0,v1));
                    rmax1=fmaxf(rmax1,fmaxf(v2,v3));
                }
            } else {
#pragma unroll
                for(int nt=0;nt<8;nt++){
                    int cl = nt*8 + 2*(lane&3);
                    float ms0=sp[cl], ms1=sp[cl+1];
                    float v0=s[nt][0] - ms0;
                    float v1=s[nt][1] - ms1;
                    float v2=s[nt][2] - ms0;
                    float v3=s[nt][3] - ms1;
                    s[nt][0]=v0; s[nt][1]=v1; s[nt][2]=v2; s[nt][3]=v3;
                    rmax0=fmaxf(rmax0,fmaxf(v0,v1));
                    rmax1=fmaxf(rmax1,fmaxf(v2,v3));
                }
            }
            rmax0=fmaxf(rmax0,__shfl_xor_sync(0xffffffffu,rmax0,1));
            rmax0=fmaxf(rmax0,__shfl_xor_sync(0xffffffffu,rmax0,2));
            rmax1=fmaxf(rmax1,__shfl_xor_sync(0xffffffffu,rmax1,1));
            rmax1=fmaxf(rmax1,__shfl_xor_sync(0xffffffffu,rmax1,2));

            float mn0=fmaxf(m_[0],rmax0), mn1=fmaxf(m_[1],rmax1);
            float corr0=fexp2(m_[0]-mn0), corr1=fexp2(m_[1]-mn1);
            m_[0]=mn0; m_[1]=mn1;

            // ---- exp2 in f16x2 -> P stays in registers (A-fragment layout) ----
            unsigned eh01[8], eh23[8];
            float rs0=0.f, rs1=0.f;
#pragma unroll
            for(int nt=0;nt<8;nt++){
                half2 e01 = h2exp2(__floats2half2_rn(s[nt][0]-mn0, s[nt][1]-mn0));
                half2 e23 = h2exp2(__floats2half2_rn(s[nt][2]-mn1, s[nt][3]-mn1));
                eh01[nt] = *(unsigned*)&e01;
                eh23[nt] = *(unsigned*)&e23;
                float2 f01 = __half22float2(e01);
                float2 f23 = __half22float2(e23);
                rs0 += f01.x + f01.y;
                rs1 += f23.x + f23.y;
            }
            rs0+=__shfl_xor_sync(0xffffffffu,rs0,1);
            rs0+=__shfl_xor_sync(0xffffffffu,rs0,2);
            rs1+=__shfl_xor_sync(0xffffffffu,rs1,1);
            rs1+=__shfl_xor_sync(0xffffffffu,rs1,2);
            l_[0]=l_[0]*corr0+rs0; l_[1]=l_[1]*corr1+rs1;
#pragma unroll
            for(int nt=0;nt<8;nt++){
                o[nt][0]*=corr0; o[nt][1]*=corr0;
                o[nt][2]*=corr1; o[nt][3]*=corr1;
            }

            // ---- O += P V  (P fragments direct from registers) ----
#pragma unroll
            for(int ks=0;ks<4;ks++){
                unsigned pf[4] = {eh01[2*ks], eh23[2*ks], eh01[2*ks+1], eh23[2*ks+1]};
                uint32_t vbase = AV + kvb + vRow[ks]*128;
                int vSwz = vRow[ks]&7;
#pragma unroll
                for(int ntp=0;ntp<4;ntp++){
                    unsigned bf[4];
                    ldsm_x4t(bf, sb + vbase + 16*((2*ntp + g16) ^ vSwz));
                    mma16(o[2*ntp+0], pf, &bf[0]);
                    mma16(o[2*ntp+1], pf, &bf[2]);
                }
            }
        }
    }

    // ---- normalize + write half [B,L,D] ----
    float inv0=1.f/l_[0], inv1=1.f/l_[1];
#pragma unroll
    for(int nt=0;nt<8;nt++){
        int dd = nt*8 + 2*(lane&3);
        *(half2*)&outp[(size_t)(b*L_+r0g)*D_ + h*DH + dd] =
            __floats2half2_rn(o[nt][0]*inv0, o[nt][1]*inv0);
        *(half2*)&outp[(size_t)(b*L_+r1g)*D_ + h*DH + dd] =
            __floats2half2_rn(o[nt][2]*inv1, o[nt][3]*inv1);
    }
}

// -------------------- launch --------------------
extern "C" void kernel_launch(void* const* d_in, const int* in_sizes, int n_in,
                              void* d_out, int out_size) {
    const float* q  = (const float*)d_in[0];
    const float* k  = (const float*)d_in[1];
    const float* v  = (const float*)d_in[2];
    const unsigned char* pad = (const unsigned char*)d_in[3];
    const float* Wq = (const float*)d_in[4];
    const float* bq = (const float*)d_in[5];
    const float* Wk = (const float*)d_in[6];
    const float* bk = (const float*)d_in[7];
    const float* Wv = (const float*)d_in[8];
    const float* bv = (const float*)d_in[9];
    const float* Wo = (const float*)d_in[10];
    const float* bo = (const float*)d_in[11];
    float* out = (float*)d_out;

    __half *p_qpe, *p_kpe, *p_vr, *p_Qh, *p_Kh, *p_Vh, *p_attn, *p_Wt;
    cudaGetSymbolAddress((void**)&p_qpe,  g_qpe);
    cudaGetSymbolAddress((void**)&p_kpe,  g_kpe);
    cudaGetSymbolAddress((void**)&p_vr,   g_vr);
    cudaGetSymbolAddress((void**)&p_Qh,   g_Qh);
    cudaGetSymbolAddress((void**)&p_Kh,   g_Kh);
    cudaGetSymbolAddress((void**)&p_Vh,   g_Vh);
    cudaGetSymbolAddress((void**)&p_attn, g_attn);
    cudaGetSymbolAddress((void**)&p_Wt,   g_Wt);

    cudaFuncSetAttribute(attn_h, cudaFuncAttributeMaxDynamicSharedMemorySize, ATTN_SMEM);
    cudaFuncSetAttribute(gemm_h5<0>, cudaFuncAttributeMaxDynamicSharedMemorySize, G_SMEM);
    cudaFuncSetAttribute(gemm_h5<1>, cudaFuncAttributeMaxDynamicSharedMemorySize, G_SMEM);

    // 0) weight transposes -> half [N][K]
    transpose_w4<<<dim3(32,32,4), dim3(32,8)>>>(Wq, Wk, Wv, Wo);

    // 1) positional encodings -> half
    int pe_threads = M_ * (D_ / 2);
    pe_add_kernel<<<(pe_threads + 255) / 256, 256>>>(q, k, v);

    // 2) fused QKV projections -> head layout (half); Q pre-scaled by 0.125*log2e
    gemm_h5<1><<<dim3(8, 64, 3), 128, G_SMEM>>>(
        p_qpe, p_kpe, p_vr, p_Wt, bq, bk, bv,
        (void*)p_Qh, (void*)p_Kh, (void*)p_Vh, 0.18033688f);

    // 3) fused causal flash attention (register-resident P)
    attn_h<<<dim3(L_ / 128, B_ * H_), 256, ATTN_SMEM>>>(pad, p_attn);

    // 4) output projection -> fp32 d_out
    gemm_h5<0><<<dim3(8, 64, 1), 128, G_SMEM>>>(
        p_attn, nullptr, nullptr, p_Wt, bo, nullptr, nullptr,
        (void*)out, nullptr, nullptr, 1.0f);
}

// round 11
// speedup vs baseline: 3.5752x; 1.0419x over previous
#include <cuda_runtime.h>
#include <cuda_fp16.h>
#include <math.h>
#include <stdint.h>

#define B_  4
#define L_  2048
#define D_  1024
#define H_  16
#define DH  64
#define M_  (B_*L_)        /* 8192 */
#define NEG 1e7f

// -------------------- scratch (all half) --------------------
__device__ __half g_qpe[M_*D_];
__device__ __half g_kpe[M_*D_];
__device__ __half g_vr [M_*D_];
__device__ __half g_Qh[M_*D_];    // [B,H,L,DH]  (Q pre-scaled by 0.125*log2e)
__device__ __half g_Kh[M_*D_];
__device__ __half g_Vh[M_*D_];
__device__ __half g_attn[M_*D_];  // [B,L,D]
__device__ __half g_Wt[4*D_*D_];  // transposed weights [N][K]

// -------------------- helpers --------------------
__device__ __forceinline__ void mma16(float* c, const unsigned* a, const unsigned* b){
    asm volatile("mma.sync.aligned.m16n8k16.row.col.f32.f16.f16.f32 "
        "{%0,%1,%2,%3}, {%4,%5,%6,%7}, {%8,%9}, {%0,%1,%2,%3};"
        : "+f"(c[0]),"+f"(c[1]),"+f"(c[2]),"+f"(c[3])
        : "r"(a[0]),"r"(a[1]),"r"(a[2]),"r"(a[3]),"r"(b[0]),"r"(b[1]));
}
__device__ __forceinline__ void ldsm_x4(unsigned* r, uint32_t a){
    asm volatile("ldmatrix.sync.aligned.m8n8.x4.shared.b16 {%0,%1,%2,%3}, [%4];"
        : "=r"(r[0]),"=r"(r[1]),"=r"(r[2]),"=r"(r[3]) : "r"(a));
}
__device__ __forceinline__ void ldsm_x4t(unsigned* r, uint32_t a){
    asm volatile("ldmatrix.sync.aligned.m8n8.x4.trans.shared.b16 {%0,%1,%2,%3}, [%4];"
        : "=r"(r[0]),"=r"(r[1]),"=r"(r[2]),"=r"(r[3]) : "r"(a));
}
__device__ __forceinline__ uint32_t smem_u32(const void* p){
    uint32_t a; asm("{ .reg .u64 t; cvta.to.shared.u64 t, %1; cvt.u32.u64 %0, t; }"
                    : "=r"(a) : "l"(p)); return a;
}
__device__ __forceinline__ void cp16(uint32_t dst, const void* src){
    asm volatile("cp.async.cg.shared.global [%0], [%1], 16;" :: "r"(dst), "l"(src));
}
#define CP_COMMIT() asm volatile("cp.async.commit_group;" ::: "memory")
#define CP_WAIT1()  asm volatile("cp.async.wait_group 1;" ::: "memory")
#define CP_WAIT0()  asm volatile("cp.async.wait_group 0;" ::: "memory")
__device__ __forceinline__ float fexp2(float x){
    float y; asm("ex2.approx.ftz.f32 %0, %1;" : "=f"(y) : "f"(x)); return y;
}

// -------------------- PE add (fp32 math -> half) --------------------
__global__ void pe_add_kernel(const float* __restrict__ q, const float* __restrict__ k,
                              const float* __restrict__ v) {
    int i = blockIdx.x * blockDim.x + threadIdx.x;
    const int NF = D_ / 2;
    if (i >= M_ * NF) return;
    int row = i / NF;
    int f   = i - row * NF;
    int l   = row & (L_ - 1);
    const float kC = 9.210340371976184f / 512.0f;
    float ang = (float)l * expf(-(float)f * kC);
    float s, c;
    sincosf(ang, &s, &c);
    int base = row * D_ + 2 * f;
    *(half2*)&g_qpe[base] = __floats2half2_rn(q[base] + s, q[base+1] + c);
    *(half2*)&g_kpe[base] = __floats2half2_rn(k[base] + s, k[base+1] + c);
    *(half2*)&g_vr[base]  = __floats2half2_rn(v[base],     v[base+1]);
}

// -------------------- weight transpose -> half [N][K] --------------------
__global__ void transpose_w4(const float* __restrict__ W0, const float* __restrict__ W1,
                             const float* __restrict__ W2, const float* __restrict__ W3){
    __shared__ float t[32][33];
    const float* W = (blockIdx.z==0)?W0:(blockIdx.z==1)?W1:(blockIdx.z==2)?W2:W3;
    __half* O = g_Wt + (size_t)blockIdx.z * D_ * D_;
    int x0 = blockIdx.x*32, y0 = blockIdx.y*32;
    int tx = threadIdx.x, ty0 = threadIdx.y;   // (32, 8)
#pragma unroll
    for (int i=0;i<4;i++){ int ty=ty0+i*8; t[ty][tx] = W[(size_t)(y0+ty)*D_ + x0+tx]; }
    __syncthreads();
#pragma unroll
    for (int i=0;i<2;i++){
        int kk = ty0 + i*8;
        half2 h = __floats2half2_rn(t[2*kk][tx], t[2*kk+1][tx]);
        *(half2*)&O[(size_t)(x0+tx)*D_ + y0 + 2*kk] = h;
    }
}

// -------------------- fp16 GEMM: BK=64, 3-stage cp.async, optional QKV fusion -----
#define GS 32768
#define G_SMEM (3*GS)

template<int QKV>
__global__ void __launch_bounds__(128, 2)
gemm_h5(const __half* __restrict__ A0, const __half* __restrict__ A1,
        const __half* __restrict__ A2, const __half* __restrict__ WtBase,
        const float* __restrict__ b0, const float* __restrict__ b1,
        const float* __restrict__ b2,
        void* O0, void* O1, void* O2, float qs){
    extern __shared__ __align__(128) char smem[];
    uint32_t sb = smem_u32(smem);
    int z = QKV ? blockIdx.z : 0;
    const __half* A    = (z==0)?A0:(z==1)?A1:A2;
    const __half* Wt   = WtBase + (size_t)(QKV ? z : 3) * D_ * D_;
    const float*  bias = (z==0)?b0:(z==1)?b1:b2;
    void* Cv           = (z==0)?O0:(z==1)?O1:O2;
    float oscale       = (QKV && z==0) ? qs : 1.f;

    int tid=threadIdx.x, lane=tid&31;
    int warp=tid>>5, wm=warp>>1, wn=warp&1;
    int bm=blockIdx.y*128, bn=blockIdx.x*128;

    const __half* Ab = A  + (size_t)bm * D_;
    const __half* Bb = Wt + (size_t)bn * D_;

    float acc[4][8][4];
#pragma unroll
    for(int i=0;i<4;i++)
#pragma unroll
      for(int j=0;j<8;j++)
#pragma unroll
        for(int r=0;r<4;r++) acc[i][j][r]=0.f;

    int prr = tid>>3, prc = tid&7;
    uint32_t stoff[8]; int prow[8];
#pragma unroll
    for(int it=0;it<8;it++){
        int r = prr + 16*it;
        prow[it] = r;
        stoff[it] = r*128 + 16*(prc ^ (r&7));
    }

    int l7=lane&7, g8=(lane>>3)&1, g16=lane>>4;
    uint32_t aRow[4]; int aSwz[4];
#pragma unroll
    for(int mt=0;mt<4;mt++){
        int r = wm*64 + mt*16 + l7 + g8*8;
        aRow[mt] = r*128; aSwz[mt] = r&7;
    }
    uint32_t bRow[4]; int bSwz[4];
#pragma unroll
    for(int ntp=0;ntp<4;ntp++){
        int n = wn*64 + ntp*16 + l7 + g16*8;
        bRow[ntp] = 16384u + n*128; bSwz[ntp] = n&7;
    }

    auto issue=[&](int ch){
        int s = ch % 3;
        uint32_t da = sb + s*GS;
#pragma unroll
        for(int it=0;it<8;it++){
            cp16(da + stoff[it],          Ab + (size_t)prow[it]*D_ + ch*64 + prc*8);
            cp16(da + 16384 + stoff[it],  Bb + (size_t)prow[it]*D_ + ch*64 + prc*8);
        }
        CP_COMMIT();
    };

    issue(0); issue(1);

    for(int ch=0; ch<16; ch++){
        if(ch<15) CP_WAIT1(); else CP_WAIT0();
        __syncthreads();
        if(ch+2<16) issue(ch+2);
        uint32_t so = sb + (ch%3)*GS;
#pragma unroll
        for(int ks=0;ks<4;ks++){
            unsigned bf[4][4];
#pragma unroll
            for(int ntp=0;ntp<4;ntp++)
                ldsm_x4(bf[ntp], so + bRow[ntp] + 16*((2*ks+g8)^bSwz[ntp]));
#pragma unroll
            for(int mt=0;mt<4;mt++){
                unsigned af[4];
                ldsm_x4(af, so + aRow[mt] + 16*((2*ks+g16)^aSwz[mt]));
#pragma unroll
                for(int ntp=0;ntp<4;ntp++){
                    mma16(acc[mt][2*ntp+0], af, &bf[ntp][0]);
                    mma16(acc[mt][2*ntp+1], af, &bf[ntp][2]);
                }
            }
        }
    }

#pragma unroll
    for(int mt=0;mt<4;mt++){
        int r0 = bm + wm*64 + mt*16 + (lane>>2);
#pragma unroll
        for(int hf=0;hf<2;hf++){
            int m = r0 + hf*8;
            int bidx = m>>11, l = m&(L_-1);
#pragma unroll
            for(int nt=0;nt<8;nt++){
                int n = bn + wn*64 + nt*8 + 2*(lane&3);
                float2 bb = *(const float2*)&bias[n];
                float v0 = (acc[mt][nt][hf*2+0] + bb.x) * oscale;
                float v1 = (acc[mt][nt][hf*2+1] + bb.y) * oscale;
                if(QKV){
                    int h=n>>6, dd=n&63;
                    *(half2*)&((__half*)Cv)[(size_t)((bidx*H_+h)*L_+l)*DH + dd] =
                        __floats2half2_rn(v0, v1);
                } else {
                    float2 ov = make_float2(v0, v1);
                    *(float2*)&((float*)Cv)[(size_t)m*D_ + n] = ov;
                }
            }
        }
    }
}

// -------------------- fp16 flash attention: reg-P, mma row-sums, fast paths ------
// Scores in log2 units (Q pre-scaled by 0.125*log2e). 128-row Q tiles,
// K/V double buffers of 128 keys; softmax in two 64-key halves.
// Row sums come from an extra MMA against a ones fragment (no shuffles).
// smem rows: 64 halves = 128B; chunk c of row r at r*128 + 16*(c ^ (r&7)).
#define AQ 0                 /* 16KB */
#define AK 16384             /* 2 x 16KB */
#define AV 49152             /* 2 x 16KB */
#define APAD 81920           /* 128 floats */
#define AFLAG (APAD + 512)
#define ATTN_SMEM (AFLAG + 16)

__global__ void __launch_bounds__(256, 2)
attn_h(const unsigned char* __restrict__ pad, __half* __restrict__ outp){
    extern __shared__ __align__(128) char smem[];
    uint32_t sb = smem_u32(smem);
    float* spad = (float*)(smem + APAD);
    int* flagp  = (int*)(smem + AFLAG);

    int tid=threadIdx.x, lane=tid&31, warp=tid>>5;
    int qt = (int)(gridDim.x - 1) - (int)blockIdx.x;   // long blocks first
    int bh=blockIdx.y;
    int b=bh>>4, h=bh&15;
    const __half* Q = g_Qh + (size_t)bh*L_*DH;
    const __half* K = g_Kh + (size_t)bh*L_*DH;
    const __half* V = g_Vh + (size_t)bh*L_*DH;

    // async load Q tile: 128 rows x 8 chunks
#pragma unroll
    for(int t=0;t<4;t++){
        int idx=t*256+tid;
        int r=idx>>3, c=idx&7;
        cp16(sb + AQ + r*128 + 16*(c ^ (r&7)),
             Q + (size_t)(qt*128+r)*DH + c*8);
    }
    CP_COMMIT();

    auto issueKV=[&](int kt2){
        uint32_t buf = (kt2&1)*16384u;
#pragma unroll
        for(int t=0;t<4;t++){
            int idx=t*256+tid;
            int r=idx>>3, c=idx&7;
            uint32_t off = r*128 + 16*(c ^ (r&7));
            cp16(sb + AK + buf + off, K + (size_t)(kt2*128+r)*DH + c*8);
            cp16(sb + AV + buf + off, V + (size_t)(kt2*128+r)*DH + c*8);
        }
        CP_COMMIT();
    };
    issueKV(0);

    int l7=lane&7, g8=(lane>>3)&1, g16=lane>>4;
    int rqa = warp*16 + l7 + g8*8;
    uint32_t qOff = AQ + rqa*128;  int qSwz = rqa&7;
    uint32_t kOff[4]; int kSwz[4];
#pragma unroll
    for(int ntp=0;ntp<4;ntp++){
        int n = ntp*16 + l7 + g16*8;
        kOff[ntp] = AK + n*128; kSwz[ntp] = n&7;
    }
    int rq0 = lane>>2;
    int vRow[4];
#pragma unroll
    for(int ks=0;ks<4;ks++) vRow[ks] = ks*16 + l7 + g8*8;

    const unsigned onesf[2] = {0x3C003C00u, 0x3C003C00u};  // B = ones (fp16 1.0)

    float m_[2]={-1e30f,-1e30f}, l_[2]={0.f,0.f};
    float o[8][4];
#pragma unroll
    for(int i=0;i<8;i++){o[i][0]=0.f;o[i][1]=0.f;o[i][2]=0.f;o[i][3]=0.f;}
    int r0g = qt*128 + warp*16 + rq0;
    int r1g = r0g + 8;

    int nkt2 = qt+1;
    for(int kt2=0;kt2<nkt2;kt2++){
        __syncthreads();                 // all warps done with buffer (kt2+1)&1
        if(kt2+1<nkt2){ issueKV(kt2+1); CP_WAIT1(); }
        else          { CP_WAIT0(); }
        // padding flag (warp 0) + mask values (warp 1)
        if(warp==0){
            unsigned pv = ((const unsigned*)(pad + b*L_ + kt2*128))[lane];
            unsigned f = __reduce_or_sync(0xffffffffu, pv);
            if(lane==0) *flagp = (int)f;
        }
        if(warp==1){
#pragma unroll
            for(int j=0;j<4;j++){
                int idx = lane*4 + j;
                spad[idx] = pad[b*L_ + kt2*128 + idx] ? NEG : 0.f;
            }
        }
        __syncthreads();                 // KV(kt2) + flag + spad visible
        bool haspad = (*flagp) != 0;
        bool diag = (kt2 == qt);

#pragma unroll
        for(int hk=0;hk<2;hk++){
            uint32_t kvb = (kt2&1)*16384u + hk*8192u;
            const float* sp = spad + hk*64;

            // ---- S = Q K^T (log2 units) ----
            float s[8][4];
#pragma unroll
            for(int i=0;i<8;i++){s[i][0]=0.f;s[i][1]=0.f;s[i][2]=0.f;s[i][3]=0.f;}
#pragma unroll
            for(int ks=0;ks<4;ks++){
                unsigned af[4];
                ldsm_x4(af, sb + qOff + 16*((2*ks + g16) ^ qSwz));
#pragma unroll
                for(int ntp=0;ntp<4;ntp++){
                    unsigned bf[4];
                    ldsm_x4(bf, sb + kOff[ntp] + kvb + 16*((2*ks + g8) ^ kSwz[ntp]));
                    mma16(s[2*ntp+0], af, &bf[0]);
                    mma16(s[2*ntp+1], af, &bf[2]);
                }
            }

            // ---- mask + row max (block-uniform fast paths) ----
            float rmax0=-1e30f, rmax1=-1e30f;
            if(diag){
                int cbase = kt2*128 + hk*64;
                if(haspad){
#pragma unroll
                    for(int nt=0;nt<8;nt++){
                        int cl = nt*8 + 2*(lane&3);
                        int c0 = cbase + cl, c1 = c0+1;
                        float ms0=sp[cl], ms1=sp[cl+1];
                        float v0=s[nt][0] - ms0; if(c0>r0g) v0-=NEG;
                        float v1=s[nt][1] - ms1; if(c1>r0g) v1-=NEG;
                        float v2=s[nt][2] - ms0; if(c0>r1g) v2-=NEG;
                        float v3=s[nt][3] - ms1; if(c1>r1g) v3-=NEG;
                        s[nt][0]=v0; s[nt][1]=v1; s[nt][2]=v2; s[nt][3]=v3;
                        rmax0=fmaxf(rmax0,fmaxf(v0,v1));
                        rmax1=fmaxf(rmax1,fmaxf(v2,v3));
                    }
                } else {
#pragma unroll
                    for(int nt=0;nt<8;nt++){
                        int cl = nt*8 + 2*(lane&3);
                        int c0 = cbase + cl, c1 = c0+1;
                        float v0=s[nt][0]; if(c0>r0g) v0-=NEG;
                        float v1=s[nt][1]; if(c1>r0g) v1-=NEG;
                        float v2=s[nt][2]; if(c0>r1g) v2-=NEG;
                        float v3=s[nt][3]; if(c1>r1g) v3-=NEG;
                        s[nt][0]=v0; s[nt][1]=v1; s[nt][2]=v2; s[nt][3]=v3;
                        rmax0=fmaxf(rmax0,fmaxf(v0,v1));
                        rmax1=fmaxf(rmax1,fmaxf(v2,v3));
                    }
                }
            } else {
                if(haspad){
#pragma unroll
                    for(int nt=0;nt<8;nt++){
                        int cl = nt*8 + 2*(lane&3);
                        float ms0=sp[cl], ms1=sp[cl+1];
                        float v0=s[nt][0] - ms0;
                        float v1=s[nt][1] - ms1;
                        float v2=s[nt][2] - ms0;
                        float v3=s[nt][3] - ms1;
                        s[nt][0]=v0; s[nt][1]=v1; s[nt][2]=v2; s[nt][3]=v3;
                        rmax0=fmaxf(rmax0,fmaxf(v0,v1));
                        rmax1=fmaxf(rmax1,fmaxf(v2,v3));
                    }
                } else {
#pragma unroll
                    for(int nt=0;nt<8;nt++){
                        rmax0=fmaxf(rmax0,fmaxf(s[nt][0],s[nt][1]));
                        rmax1=fmaxf(rmax1,fmaxf(s[nt][2],s[nt][3]));
                    }
                }
            }

            // ---- packed half2 max reduce (2 shfl instead of 4) ----
            rmax0 = fmaxf(rmax0, -60000.f);
            rmax1 = fmaxf(rmax1, -60000.f);
            half2 mh = __floats2half2_rn(rmax0, rmax1);
            unsigned mu = *(unsigned*)&mh;
            unsigned ms1_ = __shfl_xor_sync(0xffffffffu, mu, 1);
            mh = __hmax2(mh, *(half2*)&ms1_);
            mu = *(unsigned*)&mh;
            unsigned ms2_ = __shfl_xor_sync(0xffffffffu, mu, 2);
            mh = __hmax2(mh, *(half2*)&ms2_);
            float2 rmf = __half22float2(mh);

            float mn0=fmaxf(m_[0],rmf.x), mn1=fmaxf(m_[1],rmf.y);
            float corr0=fexp2(m_[0]-mn0), corr1=fexp2(m_[1]-mn1);
            m_[0]=mn0; m_[1]=mn1;

            // ---- exp2 in f16x2 -> P stays in registers ----
            unsigned eh01[8], eh23[8];
#pragma unroll
            for(int nt=0;nt<8;nt++){
                half2 e01 = h2exp2(__floats2half2_rn(s[nt][0]-mn0, s[nt][1]-mn0));
                half2 e23 = h2exp2(__floats2half2_rn(s[nt][2]-mn1, s[nt][3]-mn1));
                eh01[nt] = *(unsigned*)&e01;
                eh23[nt] = *(unsigned*)&e23;
            }
#pragma unroll
            for(int nt=0;nt<8;nt++){
                o[nt][0]*=corr0; o[nt][1]*=corr0;
                o[nt][2]*=corr1; o[nt][3]*=corr1;
            }

            // ---- O += P V ; row sums via P*ones MMA ----
            float lsum[4]={0.f,0.f,0.f,0.f};
#pragma unroll
            for(int ks=0;ks<4;ks++){
                unsigned pf[4] = {eh01[2*ks], eh23[2*ks], eh01[2*ks+1], eh23[2*ks+1]};
                mma16(lsum, pf, onesf);
                uint32_t vbase = AV + kvb + vRow[ks]*128;
                int vSwz = vRow[ks]&7;
#pragma unroll
                for(int ntp=0;ntp<4;ntp++){
                    unsigned bf[4];
                    ldsm_x4t(bf, sb + vbase + 16*((2*ntp + g16) ^ vSwz));
                    mma16(o[2*ntp+0], pf, &bf[0]);
                    mma16(o[2*ntp+1], pf, &bf[2]);
                }
            }
            l_[0]=l_[0]*corr0+lsum[0];
            l_[1]=l_[1]*corr1+lsum[2];
        }
    }

    // ---- normalize + write half [B,L,D] ----
    float inv0=1.f/l_[0], inv1=1.f/l_[1];
#pragma unroll
    for(int nt=0;nt<8;nt++){
        int dd = nt*8 + 2*(lane&3);
        *(half2*)&outp[(size_t)(b*L_+r0g)*D_ + h*DH + dd] =
            __floats2half2_rn(o[nt][0]*inv0, o[nt][1]*inv0);
        *(half2*)&outp[(size_t)(b*L_+r1g)*D_ + h*DH + dd] =
            __floats2half2_rn(o[nt][2]*inv1, o[nt][3]*inv1);
    }
}

// -------------------- launch --------------------
extern "C" void kernel_launch(void* const* d_in, const int* in_sizes, int n_in,
                              void* d_out, int out_size) {
    const float* q  = (const float*)d_in[0];
    const float* k  = (const float*)d_in[1];
    const float* v  = (const float*)d_in[2];
    const unsigned char* pad = (const unsigned char*)d_in[3];
    const float* Wq = (const float*)d_in[4];
    const float* bq = (const float*)d_in[5];
    const float* Wk = (const float*)d_in[6];
    const float* bk = (const float*)d_in[7];
    const float* Wv = (const float*)d_in[8];
    const float* bv = (const float*)d_in[9];
    const float* Wo = (const float*)d_in[10];
    const float* bo = (const float*)d_in[11];
    float* out = (float*)d_out;

    __half *p_qpe, *p_kpe, *p_vr, *p_Qh, *p_Kh, *p_Vh, *p_attn, *p_Wt;
    cudaGetSymbolAddress((void**)&p_qpe,  g_qpe);
    cudaGetSymbolAddress((void**)&p_kpe,  g_kpe);
    cudaGetSymbolAddress((void**)&p_vr,   g_vr);
    cudaGetSymbolAddress((void**)&p_Qh,   g_Qh);
    cudaGetSymbolAddress((void**)&p_Kh,   g_Kh);
    cudaGetSymbolAddress((void**)&p_Vh,   g_Vh);
    cudaGetSymbolAddress((void**)&p_attn, g_attn);
    cudaGetSymbolAddress((void**)&p_Wt,   g_Wt);

    cudaFuncSetAttribute(attn_h, cudaFuncAttributeMaxDynamicSharedMemorySize, ATTN_SMEM);
    cudaFuncSetAttribute(gemm_h5<0>, cudaFuncAttributeMaxDynamicSharedMemorySize, G_SMEM);
    cudaFuncSetAttribute(gemm_h5<1>, cudaFuncAttributeMaxDynamicSharedMemorySize, G_SMEM);

    // 0) weight transposes -> half [N][K]
    transpose_w4<<<dim3(32,32,4), dim3(32,8)>>>(Wq, Wk, Wv, Wo);

    // 1) positional encodings -> half
    int pe_threads = M_ * (D_ / 2);
    pe_add_kernel<<<(pe_threads + 255) / 256, 256>>>(q, k, v);

    // 2) fused QKV projections -> head layout (half); Q pre-scaled by 0.125*log2e
    gemm_h5<1><<<dim3(8, 64, 3), 128, G_SMEM>>>(
        p_qpe, p_kpe, p_vr, p_Wt, bq, bk, bv,
        (void*)p_Qh, (void*)p_Kh, (void*)p_Vh, 0.18033688f);

    // 3) fused causal flash attention (register P, mma row-sums)
    attn_h<<<dim3(L_ / 128, B_ * H_), 256, ATTN_SMEM>>>(pad, p_attn);

    // 4) output projection -> fp32 d_out
    gemm_h5<0><<<dim3(8, 64, 1), 128, G_SMEM>>>(
        p_attn, nullptr, nullptr, p_Wt, bo, nullptr, nullptr,
        (void*)out, nullptr, nullptr, 1.0f);
}